// round 8
// baseline (speedup 1.0000x reference)
#include <cuda_runtime.h>
#include <cuda_fp16.h>
#include <cstdint>
#include <cstddef>

// Problem constants
#define DMODEL 1024
#define SEQ    4096
#define BATCH  4
#define NHEAD  16
#define DK     64
#define M_TOTAL (BATCH * SEQ)   // 16384
#define BH      (BATCH * NHEAD) // 64
#define NCH     16

// ---------------- scratch (static device globals; no allocation) ----------------
__device__ float g_Q[(size_t)M_TOTAL * DMODEL];
__device__ float g_K[(size_t)M_TOTAL * DMODEL];
__device__ float g_V[(size_t)M_TOTAL * DMODEL];
__device__ unsigned short g_af16[(size_t)M_TOTAL * DMODEL];   // attn output, fp16
__device__ unsigned short g_whi[(size_t)DMODEL * DMODEL];
__device__ unsigned short g_wlo[(size_t)DMODEL * DMODEL];
__device__ float g_pKV[(size_t)NCH * BH * DK * DK];
__device__ float g_pKsum[(size_t)NCH * BH * DK];
__device__ float g_KV[(size_t)BH * DK * DK];
__device__ float g_Ksum[(size_t)BH * DK];

// ---------------- helpers ----------------
__device__ __forceinline__ unsigned long long pack2(float x, float y) {
    unsigned long long r;
    asm("mov.b64 %0, {%1, %2};" : "=l"(r) : "f"(x), "f"(y));
    return r;
}
__device__ __forceinline__ void unpack2(unsigned long long v, float& x, float& y) {
    asm("mov.b64 {%0, %1}, %2;" : "=f"(x), "=f"(y) : "l"(v));
}
__device__ __forceinline__ void ffma2(unsigned long long& d,
                                      unsigned long long a,
                                      unsigned long long b) {
    asm("fma.rn.f32x2 %0, %1, %2, %0;" : "+l"(d) : "l"(a), "l"(b));
}
__device__ __forceinline__ uint32_t smem_u32(const void* p) {
    uint32_t a;
    asm("{ .reg .u64 t; cvta.to.shared.u64 t, %1; cvt.u32.u64 %0, t; }" : "=r"(a) : "l"(p));
    return a;
}
__device__ __forceinline__ uint32_t cvt_h2(float hi_val, float lo_val) {
    uint32_t r;
    asm("cvt.rn.f16x2.f32 %0, %1, %2;" : "=r"(r) : "f"(hi_val), "f"(lo_val));
    return r;   // low half = lo_val, high half = hi_val
}
__device__ __forceinline__ uint4 cvt8h(const float4& a, const float4& b) {
    uint4 r;
    r.x = cvt_h2(a.y, a.x);
    r.y = cvt_h2(a.w, a.z);
    r.z = cvt_h2(b.y, b.x);
    r.w = cvt_h2(b.w, b.z);
    return r;
}

#define LDSM_X4(r0, r1, r2, r3, addr) \
    asm volatile("ldmatrix.sync.aligned.m8n8.x4.shared.b16 {%0,%1,%2,%3}, [%4];" \
                 : "=r"(r0), "=r"(r1), "=r"(r2), "=r"(r3) : "r"(addr))

#define MMA_F16(d, a, b0, b1) \
    asm volatile("mma.sync.aligned.m16n8k16.row.col.f32.f16.f16.f32 " \
                 "{%0,%1,%2,%3}, {%4,%5,%6,%7}, {%8,%9}, {%0,%1,%2,%3};" \
                 : "+f"((d)[0]), "+f"((d)[1]), "+f"((d)[2]), "+f"((d)[3]) \
                 : "r"((a)[0]), "r"((a)[1]), "r"((a)[2]), "r"((a)[3]), \
                   "r"(b0), "r"(b1))

__device__ __forceinline__ void cpasync16(uint32_t saddr, const void* g) {
    asm volatile("cp.async.cg.shared.global [%0], [%1], 16;" :: "r"(saddr), "l"(g) : "memory");
}

// ---------------- weight split: fp32 -> (hi, lo) fp16 ----------------
__global__ void __launch_bounds__(256)
cvt_wsplit_kernel(const float* __restrict__ in, unsigned short* __restrict__ hi,
                  unsigned short* __restrict__ lo, int n4)
{
    const int i = blockIdx.x * 256 + threadIdx.x;
    if (i >= n4) return;
    float4 v = ((const float4*)in)[i];
    float h[4], r[4];
    h[0] = __half2float(__float2half_rn(v.x)); r[0] = v.x - h[0];
    h[1] = __half2float(__float2half_rn(v.y)); r[1] = v.y - h[1];
    h[2] = __half2float(__float2half_rn(v.z)); r[2] = v.z - h[2];
    h[3] = __half2float(__float2half_rn(v.w)); r[3] = v.w - h[3];
    uint2 ph, pl;
    ph.x = cvt_h2(h[1], h[0]); ph.y = cvt_h2(h[3], h[2]);
    pl.x = cvt_h2(r[1], r[0]); pl.y = cvt_h2(r[3], r[2]);
    ((uint2*)hi)[i] = ph;
    ((uint2*)lo)[i] = pl;
}

// ---------------- HMMA GEMM: C[m,n] = sum_k A[m,k] * W[n,k] (+epilogue) ----------------
// A: 1-term fp16 (AHALF ? cp.async from fp16 gmem : LDG fp32 + in-reg cvt, 1 stage ahead).
// W: 2-term fp16 (pre-split, 4-deep cp.async ring).
// CTA 128x128, 512 threads (16 warps, warp tile 32x32), K-stage 32.
#define KSTAGE 32
#define NKIT   (DMODEL / KSTAGE)           // 32
#define ROWB   80                          // smem row stride: conflict-free ldmatrix
#define SUBT   (128 * ROWB)                // 10240 B per 128x32 fp16 sub-tile
#define SLOT   (3 * SUBT)                  // A, Bhi, Blo = 30720
#define NSTAGE 4
#define GEMM_SMEM (NSTAGE * SLOT)          // 122880

template <int MODE, int AHALF>
__global__ void __launch_bounds__(512)
gemm_h2(const void* __restrict__ Asrc,
        const unsigned short* __restrict__ Bhi, const unsigned short* __restrict__ Blo,
        float* __restrict__ C, const float* __restrict__ bias)
{
    extern __shared__ char smem[];
    const uint32_t sbase = smem_u32(smem);

    const int tid  = threadIdx.x;
    const int wid  = tid >> 5;
    const int lane = tid & 31;
    const int rowBase = blockIdx.y * 128;
    const int colBase = blockIdx.x * 128;

    const int wm = (wid & 3) * 32;
    const int wn = (wid >> 2) * 32;

    const uint32_t aoff = (uint32_t)(wm + (lane & 15)) * ROWB + (uint32_t)(lane >> 4) * 16;
    const uint32_t boff = (uint32_t)(wn + (lane & 7) + ((lane >> 4) << 3)) * ROWB
                        + (uint32_t)((lane >> 3) & 1) * 16;

    // staging map: thread -> (row, 16B chunk)
    const int crow = tid >> 2;
    const int c16  = tid & 3;
    const float* gA32 = (const float*)Asrc + (size_t)(rowBase + crow) * DMODEL + c16 * 8;
    const unsigned short* gA16 = (const unsigned short*)Asrc
                               + (size_t)(rowBase + crow) * DMODEL + c16 * 8;
    const unsigned short* gBh = Bhi + (size_t)(colBase + crow) * DMODEL + c16 * 8;
    const unsigned short* gBl = Blo + (size_t)(colBase + crow) * DMODEL + c16 * 8;
    const uint32_t soff = (uint32_t)crow * ROWB + (uint32_t)c16 * 16;

    float acc[2][4][4];
#pragma unroll
    for (int i = 0; i < 2; i++)
#pragma unroll
        for (int j = 0; j < 4; j++)
#pragma unroll
            for (int r = 0; r < 4; r++) acc[i][j][r] = 0.f;

    // ---- prologue: commit B stages 0..2 as separate groups; A(0) via reg path ----
#pragma unroll
    for (int s = 0; s < NSTAGE - 1; s++) {
        const uint32_t st = sbase + s * SLOT;
        const int kt = s * KSTAGE;
        cpasync16(st + SUBT + soff,     gBh + kt);
        cpasync16(st + 2 * SUBT + soff, gBl + kt);
        if (AHALF) cpasync16(st + soff, gA16 + kt);
        asm volatile("cp.async.commit_group;" ::: "memory");
    }
    if (!AHALF) {
        float4 a0 = *(const float4*)gA32;
        float4 a1 = *(const float4*)(gA32 + 4);
        *(uint4*)(smem + soff) = cvt8h(a0, a1);
    }

    for (int it = 0; it < NKIT; ++it) {
        // stage it's group is the (it)-th commit; 2 newer groups may be pending
        asm volatile("cp.async.wait_group 2;" ::: "memory");
        __syncthreads();   // slot (it-1)&3 fully consumed by ALL warps; A(it) STS visible

        // prefetch stage it+3 into slot (it+3)&3 == (it-1)&3 (safe post-barrier)
        if (it + NSTAGE - 1 < NKIT) {
            const int s = it + NSTAGE - 1;
            const uint32_t st = sbase + (s & (NSTAGE - 1)) * SLOT;
            const int kt = s * KSTAGE;
            cpasync16(st + SUBT + soff,     gBh + kt);
            cpasync16(st + 2 * SUBT + soff, gBl + kt);
            if (AHALF) cpasync16(st + soff, gA16 + kt);
        }
        asm volatile("cp.async.commit_group;" ::: "memory");   // unconditional (tail: empty)

        // A fp32 load for stage it+1 (reg path, hidden by compute below)
        float4 na0, na1;
        if (!AHALF && it + 1 < NKIT) {
            const int kt = (it + 1) * KSTAGE;
            na0 = *(const float4*)(gA32 + kt);
            na1 = *(const float4*)(gA32 + kt + 4);
        }

        // ---- compute slot it&3 ----
        const uint32_t slot = sbase + (it & (NSTAGE - 1)) * SLOT;
        const uint32_t pA  = slot + aoff;
        const uint32_t pBh = slot + SUBT + boff;
        const uint32_t pBl = slot + 2 * SUBT + boff;

#pragma unroll
        for (int kk = 0; kk < 2; kk++) {
            const uint32_t ko = kk * 32;   // 16 fp16 = 32 bytes
            uint32_t ah[8], bh[8], bl[8];
            LDSM_X4(ah[0], ah[1], ah[2], ah[3], pA + ko);
            LDSM_X4(ah[4], ah[5], ah[6], ah[7], pA + 16 * ROWB + ko);
            LDSM_X4(bh[0], bh[1], bh[2], bh[3], pBh + ko);
            LDSM_X4(bh[4], bh[5], bh[6], bh[7], pBh + 16 * ROWB + ko);
            LDSM_X4(bl[0], bl[1], bl[2], bl[3], pBl + ko);
            LDSM_X4(bl[4], bl[5], bl[6], bl[7], pBl + 16 * ROWB + ko);
#pragma unroll
            for (int mt = 0; mt < 2; mt++)
#pragma unroll
                for (int j = 0; j < 4; j++)
                    MMA_F16(acc[mt][j], ah + mt * 4, bh[j * 2], bh[j * 2 + 1]);
#pragma unroll
            for (int mt = 0; mt < 2; mt++)
#pragma unroll
                for (int j = 0; j < 4; j++)
                    MMA_F16(acc[mt][j], ah + mt * 4, bl[j * 2], bl[j * 2 + 1]);
        }

        // stage A(it+1) into slot (it+1)&3 (read only after next barrier)
        if (!AHALF && it + 1 < NKIT) {
            char* ns = smem + ((it + 1) & (NSTAGE - 1)) * SLOT;
            *(uint4*)(ns + soff) = cvt8h(na0, na1);
        }
    }

    // ---- epilogue ----
    const int lrow = lane >> 2;
    const int lcol = (lane & 3) * 2;
#pragma unroll
    for (int mt = 0; mt < 2; mt++) {
#pragma unroll
        for (int j = 0; j < 4; j++) {
            const int col = colBase + wn + j * 8 + lcol;
#pragma unroll
            for (int half = 0; half < 2; half++) {
                const int row = rowBase + wm + mt * 16 + lrow + half * 8;
                float v0 = acc[mt][j][half * 2 + 0];
                float v1 = acc[mt][j][half * 2 + 1];
                if (MODE == 1) {
                    v0 = (v0 > 0.f) ? (v0 + 1.f) : __expf(v0);
                    v1 = (v1 > 0.f) ? (v1 + 1.f) : __expf(v1);
                } else if (MODE == 2) {
                    v0 += bias[col];
                    v1 += bias[col + 1];
                }
                *(float2*)(C + (size_t)row * DMODEL + col) = make_float2(v0, v1);
            }
        }
    }
}

// ---------------- KV partial: per (bh, chunk) sum_s K^T V over SEQ/NCH s ----------------
__global__ void __launch_bounds__(256)
kv_partial_kernel()
{
    const int bh = blockIdx.x;
    const int ch = blockIdx.y;
    const int b = bh >> 4, h = bh & 15;
    const int tid = threadIdx.x;

    __shared__ float Ksh[16][DK];
    __shared__ float Vsh[16][DK];

    const int e = tid & 63;
    const int dbase = (tid >> 6) * 16;

    unsigned long long acc[8];
    {
        const unsigned long long z = pack2(0.f, 0.f);
#pragma unroll
        for (int i = 0; i < 8; i++) acc[i] = z;
    }
    float ksum = 0.f;

    const int s0 = ch * (SEQ / NCH);
    const size_t base = ((size_t)b * SEQ + s0) * DMODEL + h * DK;
    const int lr = tid >> 4;
    const int lc = (tid & 15) * 4;

    for (int st = 0; st < SEQ / NCH; st += 16) {
        const size_t g = base + (size_t)(st + lr) * DMODEL + lc;
        *(float4*)&Ksh[lr][lc] = *(const float4*)(g_K + g);
        *(float4*)&Vsh[lr][lc] = *(const float4*)(g_V + g);
        __syncthreads();

#pragma unroll
        for (int r = 0; r < 16; r++) {
            const float vv = Vsh[r][e];
            const unsigned long long vvp = pack2(vv, vv);
            const ulonglong2 kA = *(const ulonglong2*)&Ksh[r][dbase];
            const ulonglong2 kB = *(const ulonglong2*)&Ksh[r][dbase + 4];
            const ulonglong2 kC = *(const ulonglong2*)&Ksh[r][dbase + 8];
            const ulonglong2 kD = *(const ulonglong2*)&Ksh[r][dbase + 12];
            ffma2(acc[0], kA.x, vvp); ffma2(acc[1], kA.y, vvp);
            ffma2(acc[2], kB.x, vvp); ffma2(acc[3], kB.y, vvp);
            ffma2(acc[4], kC.x, vvp); ffma2(acc[5], kC.y, vvp);
            ffma2(acc[6], kD.x, vvp); ffma2(acc[7], kD.y, vvp);
        }
        if (tid < 64) {
#pragma unroll
            for (int r = 0; r < 16; r++) ksum += Ksh[r][tid];
        }
        __syncthreads();
    }

    float* pkv = g_pKV + ((size_t)ch * BH + bh) * (DK * DK);
#pragma unroll
    for (int p = 0; p < 8; p++) {
        float v0, v1;
        unpack2(acc[p], v0, v1);
        pkv[(dbase + 2 * p) * DK + e] = v0;
        pkv[(dbase + 2 * p + 1) * DK + e] = v1;
    }
    if (tid < 64) g_pKsum[((size_t)ch * BH + bh) * DK + tid] = ksum;
}

// ---------------- KV reduce ----------------
__global__ void kv_reduce_kernel()
{
    const int idx = blockIdx.x * 256 + threadIdx.x;
    const int NKV = BH * DK * DK;
    if (idx < NKV) {
        float s = 0.f;
#pragma unroll
        for (int ch = 0; ch < NCH; ch++) s += g_pKV[(size_t)ch * NKV + idx];
        g_KV[idx] = s;
    } else if (idx < NKV + BH * DK) {
        const int o = idx - NKV;
        float s = 0.f;
#pragma unroll
        for (int ch = 0; ch < NCH; ch++) s += g_pKsum[(size_t)ch * BH * DK + o];
        g_Ksum[o] = s;
    }
}

// ---------------- attention apply: out = (Q @ KV) / (Q . Ksum + eps) -> fp16 ----------------
__global__ void __launch_bounds__(256)
attn_kernel()
{
    const int bh = blockIdx.x;
    const int qt = blockIdx.y;
    const int b = bh >> 4, h = bh & 15;
    const int tid = threadIdx.x;

    __shared__ float KVs[DK * DK];
    __shared__ float Qs[DK][DK + 2];
    __shared__ float Ksm[DK];
    __shared__ float rden[DK];

    const size_t base = ((size_t)b * SEQ + qt * DK) * DMODEL + h * DK;

#pragma unroll
    for (int l = 0; l < 16; l++) {
        const int idx = tid + l * 256;
        KVs[idx] = g_KV[(size_t)bh * DK * DK + idx];
        const int q = idx >> 6, d = idx & 63;
        Qs[d][q] = g_Q[base + (size_t)q * DMODEL + d];
    }
    if (tid < DK) Ksm[tid] = g_Ksum[bh * DK + tid];
    __syncthreads();

    if (tid < DK) {
        float s = 0.f;
#pragma unroll
        for (int d = 0; d < DK; d++) s += Qs[d][tid] * Ksm[d];
        rden[tid] = 1.f / (s + 1e-6f);
    }
    __syncthreads();

    const int e = tid & 63;
    const int qg = tid >> 6;

    unsigned long long acc[8];
    {
        const unsigned long long z = pack2(0.f, 0.f);
#pragma unroll
        for (int i = 0; i < 8; i++) acc[i] = z;
    }

#pragma unroll 8
    for (int d = 0; d < DK; d++) {
        const float kv = KVs[d * DK + e];
        const unsigned long long kvp = pack2(kv, kv);
#pragma unroll
        for (int t = 0; t < 8; t++) {
            const unsigned long long qp =
                *(const unsigned long long*)&Qs[d][qg * 16 + 2 * t];
            ffma2(acc[t], qp, kvp);
        }
    }

#pragma unroll
    for (int t = 0; t < 8; t++) {
        float v0, v1;
        unpack2(acc[t], v0, v1);
        const int q0 = qg * 16 + 2 * t;
        v0 *= rden[q0];
        v1 *= rden[q0 + 1];
        unsigned short h0, h1;
        asm("cvt.rn.f16.f32 %0, %1;" : "=h"(h0) : "f"(v0));
        asm("cvt.rn.f16.f32 %0, %1;" : "=h"(h1) : "f"(v1));
        g_af16[base + (size_t)q0 * DMODEL + e] = h0;
        g_af16[base + (size_t)(q0 + 1) * DMODEL + e] = h1;
    }
}

// ---------------- launch ----------------
extern "C" void kernel_launch(void* const* d_in, const int* in_sizes, int n_in,
                              void* d_out, int out_size)
{
    const float* query = (const float*)d_in[0];
    const float* key   = (const float*)d_in[1];
    const float* value = (const float*)d_in[2];
    const float* Wq    = (const float*)d_in[3];
    const float* Wk    = (const float*)d_in[4];
    const float* Wv    = (const float*)d_in[5];
    const float* Wo    = (const float*)d_in[6];
    const float* bo    = (const float*)d_in[7];
    float* out = (float*)d_out;
    (void)in_sizes; (void)n_in; (void)out_size;

    float *pQ, *pK, *pV;
    unsigned short *whi, *wlo, *af16;
    cudaGetSymbolAddress((void**)&pQ, g_Q);
    cudaGetSymbolAddress((void**)&pK, g_K);
    cudaGetSymbolAddress((void**)&pV, g_V);
    cudaGetSymbolAddress((void**)&whi, g_whi);
    cudaGetSymbolAddress((void**)&wlo, g_wlo);
    cudaGetSymbolAddress((void**)&af16, g_af16);

    cudaFuncSetAttribute(gemm_h2<0,0>, cudaFuncAttributeMaxDynamicSharedMemorySize, GEMM_SMEM);
    cudaFuncSetAttribute(gemm_h2<1,0>, cudaFuncAttributeMaxDynamicSharedMemorySize, GEMM_SMEM);
    cudaFuncSetAttribute(gemm_h2<2,1>, cudaFuncAttributeMaxDynamicSharedMemorySize, GEMM_SMEM);

    const int n4w = DMODEL * DMODEL / 4;
    const int cb = 256;
    const dim3 ggrid(DMODEL / 128, M_TOTAL / 128);   // (8, 128)

    // Q = phi(query @ Wq^T)
    cvt_wsplit_kernel<<<(n4w + cb - 1) / cb, cb>>>(Wq, whi, wlo, n4w);
    gemm_h2<1,0><<<ggrid, 512, GEMM_SMEM>>>(query, whi, wlo, pQ, nullptr);

    // K = phi(key @ Wk^T)
    cvt_wsplit_kernel<<<(n4w + cb - 1) / cb, cb>>>(Wk, whi, wlo, n4w);
    gemm_h2<1,0><<<ggrid, 512, GEMM_SMEM>>>(key, whi, wlo, pK, nullptr);

    // V = value @ Wv^T
    cvt_wsplit_kernel<<<(n4w + cb - 1) / cb, cb>>>(Wv, whi, wlo, n4w);
    gemm_h2<0,0><<<ggrid, 512, GEMM_SMEM>>>(value, whi, wlo, pV, nullptr);

    // linear attention core
    kv_partial_kernel<<<dim3(BH, NCH), 256>>>();
    kv_reduce_kernel<<<(BH * DK * DK + BH * DK + 255) / 256, 256>>>();
    attn_kernel<<<dim3(BH, SEQ / DK), 256>>>();

    // out = attn @ Wo^T + bo  (A pre-quantized fp16 by attn_kernel)
    cvt_wsplit_kernel<<<(n4w + cb - 1) / cb, cb>>>(Wo, whi, wlo, n4w);
    gemm_h2<2,1><<<ggrid, 512, GEMM_SMEM>>>(af16, whi, wlo, out, bo);
}

// round 9
// speedup vs baseline: 1.6941x; 1.6941x over previous
#include <cuda_runtime.h>
#include <cuda_fp16.h>
#include <cstdint>
#include <cstddef>

// Problem constants
#define DMODEL 1024
#define SEQ    4096
#define BATCH  4
#define NHEAD  16
#define DK     64
#define M_TOTAL (BATCH * SEQ)   // 16384
#define BH      (BATCH * NHEAD) // 64
#define NCH     16

// ---------------- scratch (static device globals; no allocation) ----------------
__device__ float g_Q[(size_t)M_TOTAL * DMODEL];
__device__ float g_K[(size_t)M_TOTAL * DMODEL];
__device__ float g_V[(size_t)M_TOTAL * DMODEL];
__device__ unsigned short g_af16[(size_t)M_TOTAL * DMODEL];   // attn output, fp16
__device__ unsigned short g_wh[(size_t)DMODEL * DMODEL];      // weight, fp16
__device__ float g_pKV[(size_t)NCH * BH * DK * DK];
__device__ float g_pKsum[(size_t)NCH * BH * DK];
__device__ float g_KV[(size_t)BH * DK * DK];
__device__ float g_Ksum[(size_t)BH * DK];

// ---------------- helpers ----------------
__device__ __forceinline__ unsigned long long pack2(float x, float y) {
    unsigned long long r;
    asm("mov.b64 %0, {%1, %2};" : "=l"(r) : "f"(x), "f"(y));
    return r;
}
__device__ __forceinline__ void unpack2(unsigned long long v, float& x, float& y) {
    asm("mov.b64 {%0, %1}, %2;" : "=f"(x), "=f"(y) : "l"(v));
}
__device__ __forceinline__ void ffma2(unsigned long long& d,
                                      unsigned long long a,
                                      unsigned long long b) {
    asm("fma.rn.f32x2 %0, %1, %2, %0;" : "+l"(d) : "l"(a), "l"(b));
}
__device__ __forceinline__ uint32_t smem_u32(const void* p) {
    uint32_t a;
    asm("{ .reg .u64 t; cvta.to.shared.u64 t, %1; cvt.u32.u64 %0, t; }" : "=r"(a) : "l"(p));
    return a;
}
__device__ __forceinline__ uint32_t cvt_h2(float hi_val, float lo_val) {
    uint32_t r;
    asm("cvt.rn.f16x2.f32 %0, %1, %2;" : "=r"(r) : "f"(hi_val), "f"(lo_val));
    return r;   // low half = lo_val, high half = hi_val
}
__device__ __forceinline__ uint4 cvt8h(const float4& a, const float4& b) {
    uint4 r;
    r.x = cvt_h2(a.y, a.x);
    r.y = cvt_h2(a.w, a.z);
    r.z = cvt_h2(b.y, b.x);
    r.w = cvt_h2(b.w, b.z);
    return r;
}

#define LDSM_X4(r0, r1, r2, r3, addr) \
    asm volatile("ldmatrix.sync.aligned.m8n8.x4.shared.b16 {%0,%1,%2,%3}, [%4];" \
                 : "=r"(r0), "=r"(r1), "=r"(r2), "=r"(r3) : "r"(addr))

#define MMA_F16(d, a, b0, b1) \
    asm volatile("mma.sync.aligned.m16n8k16.row.col.f32.f16.f16.f32 " \
                 "{%0,%1,%2,%3}, {%4,%5,%6,%7}, {%8,%9}, {%0,%1,%2,%3};" \
                 : "+f"((d)[0]), "+f"((d)[1]), "+f"((d)[2]), "+f"((d)[3]) \
                 : "r"((a)[0]), "r"((a)[1]), "r"((a)[2]), "r"((a)[3]), \
                   "r"(b0), "r"(b1))

__device__ __forceinline__ void cpasync16(uint32_t saddr, const void* g) {
    asm volatile("cp.async.cg.shared.global [%0], [%1], 16;" :: "r"(saddr), "l"(g) : "memory");
}

// ---------------- weight quantize: fp32 -> fp16 ----------------
__global__ void __launch_bounds__(256)
cvt_w_kernel(const float* __restrict__ in, unsigned short* __restrict__ outp, int n8)
{
    const int i = blockIdx.x * 256 + threadIdx.x;
    if (i >= n8) return;
    float4 a = ((const float4*)in)[2 * i];
    float4 b = ((const float4*)in)[2 * i + 1];
    ((uint4*)outp)[i] = cvt8h(a, b);
}

// ---------------- HMMA GEMM: C[m,n] = sum_k A[m,k] * W[n,k] (+epilogue) ----------------
// A: fp16 (AHALF ? cp.async from fp16 gmem : LDG fp32 + in-reg cvt + STS, 1 stage ahead).
// W: fp16 (pre-quantized, cp.async, 2-slot ring).
// CTA 128x128, 512 threads (16 warps, warp tile 32x32), K-stage 64, 16 stages.
// Register-double-buffered fragments hide LDSM latency inside the stage.
#define KSTAGE 64
#define NKIT   (DMODEL / KSTAGE)           // 16
#define ROWB   144                         // 128B row + 16B pad: conflict-free ldmatrix
#define SUBT   (128 * ROWB)                // 18432 B per 128x64 fp16 sub-tile
#define SLOT   (2 * SUBT)                  // A, B = 36864
#define NSTAGE 2
#define GEMM_SMEM (NSTAGE * SLOT)          // 73728

template <int MODE, int AHALF>
__global__ void __launch_bounds__(512)
gemm_h1(const void* __restrict__ Asrc, const unsigned short* __restrict__ Bh,
        float* __restrict__ C, const float* __restrict__ bias)
{
    extern __shared__ char smem[];
    const uint32_t sbase = smem_u32(smem);

    const int tid  = threadIdx.x;
    const int wid  = tid >> 5;
    const int lane = tid & 31;
    const int rowBase = blockIdx.y * 128;
    const int colBase = blockIdx.x * 128;

    const int wm = (wid & 3) * 32;
    const int wn = (wid >> 2) * 32;

    const uint32_t aoff = (uint32_t)(wm + (lane & 15)) * ROWB + (uint32_t)(lane >> 4) * 16;
    const uint32_t boff = (uint32_t)(wn + (lane & 7) + ((lane >> 4) << 3)) * ROWB
                        + (uint32_t)((lane >> 3) & 1) * 16;

    // staging map: 1024 chunks (128 rows x 8 x 16B) over 512 threads, 2 each
    const int idx0 = tid, idx1 = tid + 512;
    const int r0 = idx0 >> 3, c0 = idx0 & 7;
    const int r1 = idx1 >> 3, c1 = idx1 & 7;
    const float* gA0 = (const float*)Asrc + (size_t)(rowBase + r0) * DMODEL + c0 * 8;
    const float* gA1 = (const float*)Asrc + (size_t)(rowBase + r1) * DMODEL + c1 * 8;
    const unsigned short* gA16_0 = (const unsigned short*)Asrc
                                 + (size_t)(rowBase + r0) * DMODEL + c0 * 8;
    const unsigned short* gA16_1 = (const unsigned short*)Asrc
                                 + (size_t)(rowBase + r1) * DMODEL + c1 * 8;
    const unsigned short* gB0 = Bh + (size_t)(colBase + r0) * DMODEL + c0 * 8;
    const unsigned short* gB1 = Bh + (size_t)(colBase + r1) * DMODEL + c1 * 8;
    const uint32_t so0 = (uint32_t)r0 * ROWB + (uint32_t)c0 * 16;
    const uint32_t so1 = (uint32_t)r1 * ROWB + (uint32_t)c1 * 16;

    float acc[2][4][4];
#pragma unroll
    for (int i = 0; i < 2; i++)
#pragma unroll
        for (int j = 0; j < 4; j++)
#pragma unroll
            for (int r = 0; r < 4; r++) acc[i][j][r] = 0.f;

    // ---- prologue: stage 0 ----
    {
        cpasync16(sbase + SUBT + so0, gB0);
        cpasync16(sbase + SUBT + so1, gB1);
        if (AHALF) {
            cpasync16(sbase + so0, gA16_0);
            cpasync16(sbase + so1, gA16_1);
        }
        asm volatile("cp.async.commit_group;" ::: "memory");
        if (!AHALF) {
            float4 a00 = *(const float4*)gA0;
            float4 a01 = *(const float4*)(gA0 + 4);
            float4 a10 = *(const float4*)gA1;
            float4 a11 = *(const float4*)(gA1 + 4);
            *(uint4*)(smem + so0) = cvt8h(a00, a01);
            *(uint4*)(smem + so1) = cvt8h(a10, a11);
        }
        asm volatile("cp.async.wait_group 0;" ::: "memory");
    }
    __syncthreads();

    for (int it = 0; it < NKIT; ++it) {
        const uint32_t slot = sbase + (it & 1) * SLOT;

        // prefetch stage it+1 into the other slot (freed at the end of it-1)
        float4 na00, na01, na10, na11;
        if (it + 1 < NKIT) {
            const int kt = (it + 1) * KSTAGE;
            const uint32_t ns = sbase + ((it + 1) & 1) * SLOT;
            cpasync16(ns + SUBT + so0, gB0 + kt);
            cpasync16(ns + SUBT + so1, gB1 + kt);
            if (AHALF) {
                cpasync16(ns + so0, gA16_0 + kt);
                cpasync16(ns + so1, gA16_1 + kt);
            } else {
                na00 = *(const float4*)(gA0 + kt);
                na01 = *(const float4*)(gA0 + kt + 4);
                na10 = *(const float4*)(gA1 + kt);
                na11 = *(const float4*)(gA1 + kt + 4);
            }
            asm volatile("cp.async.commit_group;" ::: "memory");
        }

        // ---- compute slot it&1: 4 k16-slices, reg-double-buffered frags ----
        const uint32_t pA = slot + aoff;
        const uint32_t pB = slot + SUBT + boff;

        uint32_t ah[2][8], bb[2][8];
        LDSM_X4(ah[0][0], ah[0][1], ah[0][2], ah[0][3], pA);
        LDSM_X4(ah[0][4], ah[0][5], ah[0][6], ah[0][7], pA + 16 * ROWB);
        LDSM_X4(bb[0][0], bb[0][1], bb[0][2], bb[0][3], pB);
        LDSM_X4(bb[0][4], bb[0][5], bb[0][6], bb[0][7], pB + 16 * ROWB);

#pragma unroll
        for (int kk = 0; kk < 4; kk++) {
            const int cur = kk & 1;
            if (kk < 3) {
                const int nxt = cur ^ 1;
                const uint32_t ko = (uint32_t)(kk + 1) * 32;
                LDSM_X4(ah[nxt][0], ah[nxt][1], ah[nxt][2], ah[nxt][3], pA + ko);
                LDSM_X4(ah[nxt][4], ah[nxt][5], ah[nxt][6], ah[nxt][7], pA + 16 * ROWB + ko);
                LDSM_X4(bb[nxt][0], bb[nxt][1], bb[nxt][2], bb[nxt][3], pB + ko);
                LDSM_X4(bb[nxt][4], bb[nxt][5], bb[nxt][6], bb[nxt][7], pB + 16 * ROWB + ko);
            }
#pragma unroll
            for (int mt = 0; mt < 2; mt++)
#pragma unroll
                for (int j = 0; j < 4; j++)
                    MMA_F16(acc[mt][j], ah[cur] + mt * 4, bb[cur][j * 2], bb[cur][j * 2 + 1]);
        }

        // stage A(it+1) via reg path
        if (!AHALF && it + 1 < NKIT) {
            char* ns = smem + ((it + 1) & 1) * SLOT;
            *(uint4*)(ns + so0) = cvt8h(na00, na01);
            *(uint4*)(ns + so1) = cvt8h(na10, na11);
        }

        if (it + 1 < NKIT)
            asm volatile("cp.async.wait_group 0;" ::: "memory");
        __syncthreads();
    }

    // ---- epilogue ----
    const int lrow = lane >> 2;
    const int lcol = (lane & 3) * 2;
#pragma unroll
    for (int mt = 0; mt < 2; mt++) {
#pragma unroll
        for (int j = 0; j < 4; j++) {
            const int col = colBase + wn + j * 8 + lcol;
#pragma unroll
            for (int half = 0; half < 2; half++) {
                const int row = rowBase + wm + mt * 16 + lrow + half * 8;
                float v0 = acc[mt][j][half * 2 + 0];
                float v1 = acc[mt][j][half * 2 + 1];
                if (MODE == 1) {
                    v0 = (v0 > 0.f) ? (v0 + 1.f) : __expf(v0);
                    v1 = (v1 > 0.f) ? (v1 + 1.f) : __expf(v1);
                } else if (MODE == 2) {
                    v0 += bias[col];
                    v1 += bias[col + 1];
                }
                *(float2*)(C + (size_t)row * DMODEL + col) = make_float2(v0, v1);
            }
        }
    }
}

// ---------------- KV partial: per (bh, chunk) sum_s K^T V over SEQ/NCH s ----------------
__global__ void __launch_bounds__(256)
kv_partial_kernel()
{
    const int bh = blockIdx.x;
    const int ch = blockIdx.y;
    const int b = bh >> 4, h = bh & 15;
    const int tid = threadIdx.x;

    __shared__ float Ksh[16][DK];
    __shared__ float Vsh[16][DK];

    const int e = tid & 63;
    const int dbase = (tid >> 6) * 16;

    unsigned long long acc[8];
    {
        const unsigned long long z = pack2(0.f, 0.f);
#pragma unroll
        for (int i = 0; i < 8; i++) acc[i] = z;
    }
    float ksum = 0.f;

    const int s0 = ch * (SEQ / NCH);
    const size_t base = ((size_t)b * SEQ + s0) * DMODEL + h * DK;
    const int lr = tid >> 4;
    const int lc = (tid & 15) * 4;

    for (int st = 0; st < SEQ / NCH; st += 16) {
        const size_t g = base + (size_t)(st + lr) * DMODEL + lc;
        *(float4*)&Ksh[lr][lc] = *(const float4*)(g_K + g);
        *(float4*)&Vsh[lr][lc] = *(const float4*)(g_V + g);
        __syncthreads();

#pragma unroll
        for (int r = 0; r < 16; r++) {
            const float vv = Vsh[r][e];
            const unsigned long long vvp = pack2(vv, vv);
            const ulonglong2 kA = *(const ulonglong2*)&Ksh[r][dbase];
            const ulonglong2 kB = *(const ulonglong2*)&Ksh[r][dbase + 4];
            const ulonglong2 kC = *(const ulonglong2*)&Ksh[r][dbase + 8];
            const ulonglong2 kD = *(const ulonglong2*)&Ksh[r][dbase + 12];
            ffma2(acc[0], kA.x, vvp); ffma2(acc[1], kA.y, vvp);
            ffma2(acc[2], kB.x, vvp); ffma2(acc[3], kB.y, vvp);
            ffma2(acc[4], kC.x, vvp); ffma2(acc[5], kC.y, vvp);
            ffma2(acc[6], kD.x, vvp); ffma2(acc[7], kD.y, vvp);
        }
        if (tid < 64) {
#pragma unroll
            for (int r = 0; r < 16; r++) ksum += Ksh[r][tid];
        }
        __syncthreads();
    }

    float* pkv = g_pKV + ((size_t)ch * BH + bh) * (DK * DK);
#pragma unroll
    for (int p = 0; p < 8; p++) {
        float v0, v1;
        unpack2(acc[p], v0, v1);
        pkv[(dbase + 2 * p) * DK + e] = v0;
        pkv[(dbase + 2 * p + 1) * DK + e] = v1;
    }
    if (tid < 64) g_pKsum[((size_t)ch * BH + bh) * DK + tid] = ksum;
}

// ---------------- KV reduce ----------------
__global__ void kv_reduce_kernel()
{
    const int idx = blockIdx.x * 256 + threadIdx.x;
    const int NKV = BH * DK * DK;
    if (idx < NKV) {
        float s = 0.f;
#pragma unroll
        for (int ch = 0; ch < NCH; ch++) s += g_pKV[(size_t)ch * NKV + idx];
        g_KV[idx] = s;
    } else if (idx < NKV + BH * DK) {
        const int o = idx - NKV;
        float s = 0.f;
#pragma unroll
        for (int ch = 0; ch < NCH; ch++) s += g_pKsum[(size_t)ch * BH * DK + o];
        g_Ksum[o] = s;
    }
}

// ---------------- attention apply: out = (Q @ KV) / (Q . Ksum + eps) -> fp16 ----------------
__global__ void __launch_bounds__(256)
attn_kernel()
{
    const int bh = blockIdx.x;
    const int qt = blockIdx.y;
    const int b = bh >> 4, h = bh & 15;
    const int tid = threadIdx.x;

    __shared__ float KVs[DK * DK];
    __shared__ float Qs[DK][DK + 2];
    __shared__ float Ksm[DK];
    __shared__ float rden[DK];

    const size_t base = ((size_t)b * SEQ + qt * DK) * DMODEL + h * DK;

#pragma unroll
    for (int l = 0; l < 16; l++) {
        const int idx = tid + l * 256;
        KVs[idx] = g_KV[(size_t)bh * DK * DK + idx];
        const int q = idx >> 6, d = idx & 63;
        Qs[d][q] = g_Q[base + (size_t)q * DMODEL + d];
    }
    if (tid < DK) Ksm[tid] = g_Ksum[bh * DK + tid];
    __syncthreads();

    if (tid < DK) {
        float s = 0.f;
#pragma unroll
        for (int d = 0; d < DK; d++) s += Qs[d][tid] * Ksm[d];
        rden[tid] = 1.f / (s + 1e-6f);
    }
    __syncthreads();

    const int e = tid & 63;
    const int qg = tid >> 6;

    unsigned long long acc[8];
    {
        const unsigned long long z = pack2(0.f, 0.f);
#pragma unroll
        for (int i = 0; i < 8; i++) acc[i] = z;
    }

#pragma unroll 8
    for (int d = 0; d < DK; d++) {
        const float kv = KVs[d * DK + e];
        const unsigned long long kvp = pack2(kv, kv);
#pragma unroll
        for (int t = 0; t < 8; t++) {
            const unsigned long long qp =
                *(const unsigned long long*)&Qs[d][qg * 16 + 2 * t];
            ffma2(acc[t], qp, kvp);
        }
    }

#pragma unroll
    for (int t = 0; t < 8; t++) {
        float v0, v1;
        unpack2(acc[t], v0, v1);
        const int q0 = qg * 16 + 2 * t;
        v0 *= rden[q0];
        v1 *= rden[q0 + 1];
        unsigned short h0, h1;
        asm("cvt.rn.f16.f32 %0, %1;" : "=h"(h0) : "f"(v0));
        asm("cvt.rn.f16.f32 %0, %1;" : "=h"(h1) : "f"(v1));
        g_af16[base + (size_t)q0 * DMODEL + e] = h0;
        g_af16[base + (size_t)(q0 + 1) * DMODEL + e] = h1;
    }
}

// ---------------- launch ----------------
extern "C" void kernel_launch(void* const* d_in, const int* in_sizes, int n_in,
                              void* d_out, int out_size)
{
    const float* query = (const float*)d_in[0];
    const float* key   = (const float*)d_in[1];
    const float* value = (const float*)d_in[2];
    const float* Wq    = (const float*)d_in[3];
    const float* Wk    = (const float*)d_in[4];
    const float* Wv    = (const float*)d_in[5];
    const float* Wo    = (const float*)d_in[6];
    const float* bo    = (const float*)d_in[7];
    float* out = (float*)d_out;
    (void)in_sizes; (void)n_in; (void)out_size;

    float *pQ, *pK, *pV;
    unsigned short *wh, *af16;
    cudaGetSymbolAddress((void**)&pQ, g_Q);
    cudaGetSymbolAddress((void**)&pK, g_K);
    cudaGetSymbolAddress((void**)&pV, g_V);
    cudaGetSymbolAddress((void**)&wh, g_wh);
    cudaGetSymbolAddress((void**)&af16, g_af16);

    cudaFuncSetAttribute(gemm_h1<0,0>, cudaFuncAttributeMaxDynamicSharedMemorySize, GEMM_SMEM);
    cudaFuncSetAttribute(gemm_h1<1,0>, cudaFuncAttributeMaxDynamicSharedMemorySize, GEMM_SMEM);
    cudaFuncSetAttribute(gemm_h1<2,1>, cudaFuncAttributeMaxDynamicSharedMemorySize, GEMM_SMEM);

    const int n8w = DMODEL * DMODEL / 8;
    const int cb = 256;
    const dim3 ggrid(DMODEL / 128, M_TOTAL / 128);   // (8, 128)

    // Q = phi(query @ Wq^T)
    cvt_w_kernel<<<(n8w + cb - 1) / cb, cb>>>(Wq, wh, n8w);
    gemm_h1<1,0><<<ggrid, 512, GEMM_SMEM>>>(query, wh, pQ, nullptr);

    // K = phi(key @ Wk^T)
    cvt_w_kernel<<<(n8w + cb - 1) / cb, cb>>>(Wk, wh, n8w);
    gemm_h1<1,0><<<ggrid, 512, GEMM_SMEM>>>(key, wh, pK, nullptr);

    // V = value @ Wv^T
    cvt_w_kernel<<<(n8w + cb - 1) / cb, cb>>>(Wv, wh, n8w);
    gemm_h1<0,0><<<ggrid, 512, GEMM_SMEM>>>(value, wh, pV, nullptr);

    // linear attention core
    kv_partial_kernel<<<dim3(BH, NCH), 256>>>();
    kv_reduce_kernel<<<(BH * DK * DK + BH * DK + 255) / 256, 256>>>();
    attn_kernel<<<dim3(BH, SEQ / DK), 256>>>();

    // out = attn @ Wo^T + bo  (A pre-quantized fp16 by attn_kernel)
    cvt_w_kernel<<<(n8w + cb - 1) / cb, cb>>>(Wo, wh, n8w);
    gemm_h1<2,1><<<ggrid, 512, GEMM_SMEM>>>(af16, wh, out, bo);
}

// round 10
// speedup vs baseline: 1.7347x; 1.0240x over previous
#include <cuda_runtime.h>
#include <cuda_fp16.h>
#include <cstdint>
#include <cstddef>

// Problem constants
#define DMODEL 1024
#define SEQ    4096
#define BATCH  4
#define NHEAD  16
#define DK     64
#define M_TOTAL (BATCH * SEQ)   // 16384
#define BH      (BATCH * NHEAD) // 64
#define NCH     16

// ---------------- scratch (static device globals; no allocation) ----------------
__device__ float g_Q[(size_t)M_TOTAL * DMODEL];
__device__ float g_K[(size_t)M_TOTAL * DMODEL];
__device__ float g_V[(size_t)M_TOTAL * DMODEL];
__device__ unsigned short g_xh[(size_t)M_TOTAL * DMODEL];     // activation, fp16
__device__ unsigned short g_af16[(size_t)M_TOTAL * DMODEL];   // attn output, fp16
__device__ unsigned short g_wh[(size_t)DMODEL * DMODEL];      // weight, fp16
__device__ float g_pKV[(size_t)NCH * BH * DK * DK];
__device__ float g_pKsum[(size_t)NCH * BH * DK];
__device__ float g_KV[(size_t)BH * DK * DK];
__device__ float g_Ksum[(size_t)BH * DK];

// ---------------- helpers ----------------
__device__ __forceinline__ unsigned long long pack2(float x, float y) {
    unsigned long long r;
    asm("mov.b64 %0, {%1, %2};" : "=l"(r) : "f"(x), "f"(y));
    return r;
}
__device__ __forceinline__ void unpack2(unsigned long long v, float& x, float& y) {
    asm("mov.b64 {%0, %1}, %2;" : "=f"(x), "=f"(y) : "l"(v));
}
__device__ __forceinline__ void ffma2(unsigned long long& d,
                                      unsigned long long a,
                                      unsigned long long b) {
    asm("fma.rn.f32x2 %0, %1, %2, %0;" : "+l"(d) : "l"(a), "l"(b));
}
__device__ __forceinline__ uint32_t smem_u32(const void* p) {
    uint32_t a;
    asm("{ .reg .u64 t; cvta.to.shared.u64 t, %1; cvt.u32.u64 %0, t; }" : "=r"(a) : "l"(p));
    return a;
}
__device__ __forceinline__ uint32_t cvt_h2(float hi_val, float lo_val) {
    uint32_t r;
    asm("cvt.rn.f16x2.f32 %0, %1, %2;" : "=r"(r) : "f"(hi_val), "f"(lo_val));
    return r;   // low half = lo_val, high half = hi_val
}
__device__ __forceinline__ uint4 cvt8h(const float4& a, const float4& b) {
    uint4 r;
    r.x = cvt_h2(a.y, a.x);
    r.y = cvt_h2(a.w, a.z);
    r.z = cvt_h2(b.y, b.x);
    r.w = cvt_h2(b.w, b.z);
    return r;
}

#define LDSM_X4(r0, r1, r2, r3, addr) \
    asm volatile("ldmatrix.sync.aligned.m8n8.x4.shared.b16 {%0,%1,%2,%3}, [%4];" \
                 : "=r"(r0), "=r"(r1), "=r"(r2), "=r"(r3) : "r"(addr))

#define MMA_F16(d, a, b0, b1) \
    asm volatile("mma.sync.aligned.m16n8k16.row.col.f32.f16.f16.f32 " \
                 "{%0,%1,%2,%3}, {%4,%5,%6,%7}, {%8,%9}, {%0,%1,%2,%3};" \
                 : "+f"((d)[0]), "+f"((d)[1]), "+f"((d)[2]), "+f"((d)[3]) \
                 : "r"((a)[0]), "r"((a)[1]), "r"((a)[2]), "r"((a)[3]), \
                   "r"(b0), "r"(b1))

__device__ __forceinline__ void cpasync16(uint32_t saddr, const void* g) {
    asm volatile("cp.async.cg.shared.global [%0], [%1], 16;" :: "r"(saddr), "l"(g) : "memory");
}

// ---------------- quantize: fp32 -> fp16 (weights and activations) ----------------
__global__ void __launch_bounds__(256)
cvt_h_kernel(const float* __restrict__ in, unsigned short* __restrict__ outp, int n8)
{
    const int i = blockIdx.x * 256 + threadIdx.x;
    if (i >= n8) return;
    float4 a = ((const float4*)in)[2 * i];
    float4 b = ((const float4*)in)[2 * i + 1];
    ((uint4*)outp)[i] = cvt8h(a, b);
}

// ---------------- HMMA GEMM: C[m,n] = sum_k A[m,k] * W[n,k] (+epilogue) ----------------
// A, W: fp16 in gmem (pre-quantized), pure cp.async 2-slot ring.
// CTA 128x64, 256 threads (8 warps, warp tile 32x32), K-stage 64 -> 2 CTAs/SM.
#define KSTAGE 64
#define NKIT   (DMODEL / KSTAGE)           // 16
#define ROWB   144                         // 128B row + 16B pad: conflict-free ldmatrix
#define SUBTA  (128 * ROWB)                // 18432 B: 128x64 fp16 A sub-tile
#define SUBTB  (64 * ROWB)                 // 9216 B:  64x64 fp16 B sub-tile
#define SLOT   (SUBTA + SUBTB)             // 27648
#define GEMM_SMEM (2 * SLOT)               // 55296

template <int MODE>
__global__ void __launch_bounds__(256, 2)
gemm_h1(const unsigned short* __restrict__ Ah, const unsigned short* __restrict__ Bh,
        float* __restrict__ C, const float* __restrict__ bias)
{
    extern __shared__ char smem[];
    const uint32_t sbase = smem_u32(smem);

    const int tid  = threadIdx.x;
    const int wid  = tid >> 5;
    const int lane = tid & 31;
    const int rowBase = blockIdx.y * 128;
    const int colBase = blockIdx.x * 64;

    const int wm = (wid & 3) * 32;          // 4 warps along M
    const int wn = (wid >> 2) * 32;         // 2 warps along N

    const uint32_t aoff = (uint32_t)(wm + (lane & 15)) * ROWB + (uint32_t)(lane >> 4) * 16;
    const uint32_t boff = (uint32_t)(wn + (lane & 7) + ((lane >> 4) << 3)) * ROWB
                        + (uint32_t)((lane >> 3) & 1) * 16;

    // staging map: A 1024 chunks (4/thread), B 512 chunks (2/thread); 16B each
    int ra[4], ca[4], rb[2], cb2[2];
#pragma unroll
    for (int j = 0; j < 4; j++) { const int x = tid + 256 * j; ra[j] = x >> 3; ca[j] = x & 7; }
#pragma unroll
    for (int j = 0; j < 2; j++) { const int x = tid + 256 * j; rb[j] = x >> 3; cb2[j] = x & 7; }

    const unsigned short* gA[4];
    const unsigned short* gB[2];
    uint32_t soa[4], sob[2];
#pragma unroll
    for (int j = 0; j < 4; j++) {
        gA[j] = Ah + (size_t)(rowBase + ra[j]) * DMODEL + ca[j] * 8;
        soa[j] = (uint32_t)ra[j] * ROWB + (uint32_t)ca[j] * 16;
    }
#pragma unroll
    for (int j = 0; j < 2; j++) {
        gB[j] = Bh + (size_t)(colBase + rb[j]) * DMODEL + cb2[j] * 8;
        sob[j] = SUBTA + (uint32_t)rb[j] * ROWB + (uint32_t)cb2[j] * 16;
    }

    float acc[2][4][4];
#pragma unroll
    for (int i = 0; i < 2; i++)
#pragma unroll
        for (int j = 0; j < 4; j++)
#pragma unroll
            for (int r = 0; r < 4; r++) acc[i][j][r] = 0.f;

    // ---- prologue: stage 0 ----
#pragma unroll
    for (int j = 0; j < 4; j++) cpasync16(sbase + soa[j], gA[j]);
#pragma unroll
    for (int j = 0; j < 2; j++) cpasync16(sbase + sob[j], gB[j]);
    asm volatile("cp.async.commit_group;" ::: "memory");
    asm volatile("cp.async.wait_group 0;" ::: "memory");
    __syncthreads();

    for (int it = 0; it < NKIT; ++it) {
        const uint32_t slot = sbase + (it & 1) * SLOT;

        // prefetch stage it+1 into the other slot (freed at end of it-1)
        if (it + 1 < NKIT) {
            const int kt = (it + 1) * KSTAGE;
            const uint32_t ns = sbase + ((it + 1) & 1) * SLOT;
#pragma unroll
            for (int j = 0; j < 4; j++) cpasync16(ns + soa[j], gA[j] + kt);
#pragma unroll
            for (int j = 0; j < 2; j++) cpasync16(ns + sob[j], gB[j] + kt);
            asm volatile("cp.async.commit_group;" ::: "memory");
        }

        // ---- compute slot it&1: 4 k16-slices, reg-double-buffered frags ----
        const uint32_t pA = slot + aoff;
        const uint32_t pB = slot + SUBTA + boff;

        uint32_t ah[2][8], bb[2][8];
        LDSM_X4(ah[0][0], ah[0][1], ah[0][2], ah[0][3], pA);
        LDSM_X4(ah[0][4], ah[0][5], ah[0][6], ah[0][7], pA + 16 * ROWB);
        LDSM_X4(bb[0][0], bb[0][1], bb[0][2], bb[0][3], pB);
        LDSM_X4(bb[0][4], bb[0][5], bb[0][6], bb[0][7], pB + 16 * ROWB);

#pragma unroll
        for (int kk = 0; kk < 4; kk++) {
            const int cur = kk & 1;
            if (kk < 3) {
                const int nxt = cur ^ 1;
                const uint32_t ko = (uint32_t)(kk + 1) * 32;
                LDSM_X4(ah[nxt][0], ah[nxt][1], ah[nxt][2], ah[nxt][3], pA + ko);
                LDSM_X4(ah[nxt][4], ah[nxt][5], ah[nxt][6], ah[nxt][7], pA + 16 * ROWB + ko);
                LDSM_X4(bb[nxt][0], bb[nxt][1], bb[nxt][2], bb[nxt][3], pB + ko);
                LDSM_X4(bb[nxt][4], bb[nxt][5], bb[nxt][6], bb[nxt][7], pB + 16 * ROWB + ko);
            }
#pragma unroll
            for (int mt = 0; mt < 2; mt++)
#pragma unroll
                for (int j = 0; j < 4; j++)
                    MMA_F16(acc[mt][j], ah[cur] + mt * 4, bb[cur][j * 2], bb[cur][j * 2 + 1]);
        }

        if (it + 1 < NKIT)
            asm volatile("cp.async.wait_group 0;" ::: "memory");
        __syncthreads();
    }

    // ---- epilogue ----
    const int lrow = lane >> 2;
    const int lcol = (lane & 3) * 2;
#pragma unroll
    for (int mt = 0; mt < 2; mt++) {
#pragma unroll
        for (int j = 0; j < 4; j++) {
            const int col = colBase + wn + j * 8 + lcol;
#pragma unroll
            for (int half = 0; half < 2; half++) {
                const int row = rowBase + wm + mt * 16 + lrow + half * 8;
                float v0 = acc[mt][j][half * 2 + 0];
                float v1 = acc[mt][j][half * 2 + 1];
                if (MODE == 1) {
                    v0 = (v0 > 0.f) ? (v0 + 1.f) : __expf(v0);
                    v1 = (v1 > 0.f) ? (v1 + 1.f) : __expf(v1);
                } else if (MODE == 2) {
                    v0 += bias[col];
                    v1 += bias[col + 1];
                }
                *(float2*)(C + (size_t)row * DMODEL + col) = make_float2(v0, v1);
            }
        }
    }
}

// ---------------- KV partial: per (bh, chunk) sum_s K^T V over SEQ/NCH s ----------------
__global__ void __launch_bounds__(256)
kv_partial_kernel()
{
    const int bh = blockIdx.x;
    const int ch = blockIdx.y;
    const int b = bh >> 4, h = bh & 15;
    const int tid = threadIdx.x;

    __shared__ float Ksh[16][DK];
    __shared__ float Vsh[16][DK];

    const int e = tid & 63;
    const int dbase = (tid >> 6) * 16;

    unsigned long long acc[8];
    {
        const unsigned long long z = pack2(0.f, 0.f);
#pragma unroll
        for (int i = 0; i < 8; i++) acc[i] = z;
    }
    float ksum = 0.f;

    const int s0 = ch * (SEQ / NCH);
    const size_t base = ((size_t)b * SEQ + s0) * DMODEL + h * DK;
    const int lr = tid >> 4;
    const int lc = (tid & 15) * 4;

    for (int st = 0; st < SEQ / NCH; st += 16) {
        const size_t g = base + (size_t)(st + lr) * DMODEL + lc;
        *(float4*)&Ksh[lr][lc] = *(const float4*)(g_K + g);
        *(float4*)&Vsh[lr][lc] = *(const float4*)(g_V + g);
        __syncthreads();

#pragma unroll
        for (int r = 0; r < 16; r++) {
            const float vv = Vsh[r][e];
            const unsigned long long vvp = pack2(vv, vv);
            const ulonglong2 kA = *(const ulonglong2*)&Ksh[r][dbase];
            const ulonglong2 kB = *(const ulonglong2*)&Ksh[r][dbase + 4];
            const ulonglong2 kC = *(const ulonglong2*)&Ksh[r][dbase + 8];
            const ulonglong2 kD = *(const ulonglong2*)&Ksh[r][dbase + 12];
            ffma2(acc[0], kA.x, vvp); ffma2(acc[1], kA.y, vvp);
            ffma2(acc[2], kB.x, vvp); ffma2(acc[3], kB.y, vvp);
            ffma2(acc[4], kC.x, vvp); ffma2(acc[5], kC.y, vvp);
            ffma2(acc[6], kD.x, vvp); ffma2(acc[7], kD.y, vvp);
        }
        if (tid < 64) {
#pragma unroll
            for (int r = 0; r < 16; r++) ksum += Ksh[r][tid];
        }
        __syncthreads();
    }

    float* pkv = g_pKV + ((size_t)ch * BH + bh) * (DK * DK);
#pragma unroll
    for (int p = 0; p < 8; p++) {
        float v0, v1;
        unpack2(acc[p], v0, v1);
        pkv[(dbase + 2 * p) * DK + e] = v0;
        pkv[(dbase + 2 * p + 1) * DK + e] = v1;
    }
    if (tid < 64) g_pKsum[((size_t)ch * BH + bh) * DK + tid] = ksum;
}

// ---------------- KV reduce ----------------
__global__ void kv_reduce_kernel()
{
    const int idx = blockIdx.x * 256 + threadIdx.x;
    const int NKV = BH * DK * DK;
    if (idx < NKV) {
        float s = 0.f;
#pragma unroll
        for (int ch = 0; ch < NCH; ch++) s += g_pKV[(size_t)ch * NKV + idx];
        g_KV[idx] = s;
    } else if (idx < NKV + BH * DK) {
        const int o = idx - NKV;
        float s = 0.f;
#pragma unroll
        for (int ch = 0; ch < NCH; ch++) s += g_pKsum[(size_t)ch * BH * DK + o];
        g_Ksum[o] = s;
    }
}

// ---------------- attention apply: out = (Q @ KV) / (Q . Ksum + eps) -> fp16 ----------------
__global__ void __launch_bounds__(256)
attn_kernel()
{
    const int bh = blockIdx.x;
    const int qt = blockIdx.y;
    const int b = bh >> 4, h = bh & 15;
    const int tid = threadIdx.x;

    __shared__ float KVs[DK * DK];
    __shared__ float Qs[DK][DK + 2];
    __shared__ float Ksm[DK];
    __shared__ float rden[DK];

    const size_t base = ((size_t)b * SEQ + qt * DK) * DMODEL + h * DK;

#pragma unroll
    for (int l = 0; l < 16; l++) {
        const int idx = tid + l * 256;
        KVs[idx] = g_KV[(size_t)bh * DK * DK + idx];
        const int q = idx >> 6, d = idx & 63;
        Qs[d][q] = g_Q[base + (size_t)q * DMODEL + d];
    }
    if (tid < DK) Ksm[tid] = g_Ksum[bh * DK + tid];
    __syncthreads();

    if (tid < DK) {
        float s = 0.f;
#pragma unroll
        for (int d = 0; d < DK; d++) s += Qs[d][tid] * Ksm[d];
        rden[tid] = 1.f / (s + 1e-6f);
    }
    __syncthreads();

    const int e = tid & 63;
    const int qg = tid >> 6;

    unsigned long long acc[8];
    {
        const unsigned long long z = pack2(0.f, 0.f);
#pragma unroll
        for (int i = 0; i < 8; i++) acc[i] = z;
    }

#pragma unroll 8
    for (int d = 0; d < DK; d++) {
        const float kv = KVs[d * DK + e];
        const unsigned long long kvp = pack2(kv, kv);
#pragma unroll
        for (int t = 0; t < 8; t++) {
            const unsigned long long qp =
                *(const unsigned long long*)&Qs[d][qg * 16 + 2 * t];
            ffma2(acc[t], qp, kvp);
        }
    }

#pragma unroll
    for (int t = 0; t < 8; t++) {
        float v0, v1;
        unpack2(acc[t], v0, v1);
        const int q0 = qg * 16 + 2 * t;
        v0 *= rden[q0];
        v1 *= rden[q0 + 1];
        unsigned short h0, h1;
        asm("cvt.rn.f16.f32 %0, %1;" : "=h"(h0) : "f"(v0));
        asm("cvt.rn.f16.f32 %0, %1;" : "=h"(h1) : "f"(v1));
        g_af16[base + (size_t)q0 * DMODEL + e] = h0;
        g_af16[base + (size_t)(q0 + 1) * DMODEL + e] = h1;
    }
}

// ---------------- launch ----------------
extern "C" void kernel_launch(void* const* d_in, const int* in_sizes, int n_in,
                              void* d_out, int out_size)
{
    const float* query = (const float*)d_in[0];
    const float* key   = (const float*)d_in[1];
    const float* value = (const float*)d_in[2];
    const float* Wq    = (const float*)d_in[3];
    const float* Wk    = (const float*)d_in[4];
    const float* Wv    = (const float*)d_in[5];
    const float* Wo    = (const float*)d_in[6];
    const float* bo    = (const float*)d_in[7];
    float* out = (float*)d_out;
    (void)in_sizes; (void)n_in; (void)out_size;

    float *pQ, *pK, *pV;
    unsigned short *xh, *wh, *af16;
    cudaGetSymbolAddress((void**)&pQ, g_Q);
    cudaGetSymbolAddress((void**)&pK, g_K);
    cudaGetSymbolAddress((void**)&pV, g_V);
    cudaGetSymbolAddress((void**)&xh, g_xh);
    cudaGetSymbolAddress((void**)&wh, g_wh);
    cudaGetSymbolAddress((void**)&af16, g_af16);

    cudaFuncSetAttribute(gemm_h1<0>, cudaFuncAttributeMaxDynamicSharedMemorySize, GEMM_SMEM);
    cudaFuncSetAttribute(gemm_h1<1>, cudaFuncAttributeMaxDynamicSharedMemorySize, GEMM_SMEM);
    cudaFuncSetAttribute(gemm_h1<2>, cudaFuncAttributeMaxDynamicSharedMemorySize, GEMM_SMEM);

    const int n8w = DMODEL * DMODEL / 8;
    const int n8a = M_TOTAL * DMODEL / 8;
    const int cb = 256;
    const dim3 ggrid(DMODEL / 64, M_TOTAL / 128);   // (16, 128) = 2048 CTAs

    // Q = phi(query @ Wq^T)
    cvt_h_kernel<<<(n8a + cb - 1) / cb, cb>>>(query, xh, n8a);
    cvt_h_kernel<<<(n8w + cb - 1) / cb, cb>>>(Wq, wh, n8w);
    gemm_h1<1><<<ggrid, 256, GEMM_SMEM>>>(xh, wh, pQ, nullptr);

    // K = phi(key @ Wk^T)
    cvt_h_kernel<<<(n8a + cb - 1) / cb, cb>>>(key, xh, n8a);
    cvt_h_kernel<<<(n8w + cb - 1) / cb, cb>>>(Wk, wh, n8w);
    gemm_h1<1><<<ggrid, 256, GEMM_SMEM>>>(xh, wh, pK, nullptr);

    // V = value @ Wv^T
    cvt_h_kernel<<<(n8a + cb - 1) / cb, cb>>>(value, xh, n8a);
    cvt_h_kernel<<<(n8w + cb - 1) / cb, cb>>>(Wv, wh, n8w);
    gemm_h1<0><<<ggrid, 256, GEMM_SMEM>>>(xh, wh, pV, nullptr);

    // linear attention core
    kv_partial_kernel<<<dim3(BH, NCH), 256>>>();
    kv_reduce_kernel<<<(BH * DK * DK + BH * DK + 255) / 256, 256>>>();
    attn_kernel<<<dim3(BH, SEQ / DK), 256>>>();

    // out = attn @ Wo^T + bo  (A pre-quantized fp16 by attn_kernel)
    cvt_h_kernel<<<(n8w + cb - 1) / cb, cb>>>(Wo, wh, n8w);
    gemm_h1<2><<<ggrid, 256, GEMM_SMEM>>>(af16, wh, out, bo);
}

// round 11
// speedup vs baseline: 1.9920x; 1.1483x over previous
#include <cuda_runtime.h>
#include <cuda_fp16.h>
#include <cstdint>
#include <cstddef>

// Problem constants
#define DMODEL 1024
#define SEQ    4096
#define BATCH  4
#define NHEAD  16
#define DK     64
#define M_TOTAL (BATCH * SEQ)   // 16384
#define BH      (BATCH * NHEAD) // 64
#define NCH     16

// ---------------- scratch (static device globals; no allocation) ----------------
__device__ float g_Q[(size_t)M_TOTAL * DMODEL];
__device__ float g_K[(size_t)M_TOTAL * DMODEL];
__device__ float g_V[(size_t)M_TOTAL * DMODEL];
__device__ unsigned short g_xh[(size_t)M_TOTAL * DMODEL];     // activation, fp16
__device__ unsigned short g_af16[(size_t)M_TOTAL * DMODEL];   // attn output, fp16
__device__ unsigned short g_wh[(size_t)DMODEL * DMODEL];      // weight, fp16
__device__ float g_pKV[(size_t)NCH * BH * DK * DK];
__device__ float g_pKsum[(size_t)NCH * BH * DK];
__device__ float g_KV[(size_t)BH * DK * DK];
__device__ float g_Ksum[(size_t)BH * DK];

// ---------------- helpers ----------------
__device__ __forceinline__ unsigned long long pack2(float x, float y) {
    unsigned long long r;
    asm("mov.b64 %0, {%1, %2};" : "=l"(r) : "f"(x), "f"(y));
    return r;
}
__device__ __forceinline__ void unpack2(unsigned long long v, float& x, float& y) {
    asm("mov.b64 {%0, %1}, %2;" : "=f"(x), "=f"(y) : "l"(v));
}
__device__ __forceinline__ void ffma2(unsigned long long& d,
                                      unsigned long long a,
                                      unsigned long long b) {
    asm("fma.rn.f32x2 %0, %1, %2, %0;" : "+l"(d) : "l"(a), "l"(b));
}
__device__ __forceinline__ uint32_t smem_u32(const void* p) {
    uint32_t a;
    asm("{ .reg .u64 t; cvta.to.shared.u64 t, %1; cvt.u32.u64 %0, t; }" : "=r"(a) : "l"(p));
    return a;
}
__device__ __forceinline__ uint32_t cvt_h2(float hi_val, float lo_val) {
    uint32_t r;
    asm("cvt.rn.f16x2.f32 %0, %1, %2;" : "=r"(r) : "f"(hi_val), "f"(lo_val));
    return r;   // low half = lo_val, high half = hi_val
}
__device__ __forceinline__ uint4 cvt8h(const float4& a, const float4& b) {
    uint4 r;
    r.x = cvt_h2(a.y, a.x);
    r.y = cvt_h2(a.w, a.z);
    r.z = cvt_h2(b.y, b.x);
    r.w = cvt_h2(b.w, b.z);
    return r;
}

#define LDSM_X4(r0, r1, r2, r3, addr) \
    asm volatile("ldmatrix.sync.aligned.m8n8.x4.shared.b16 {%0,%1,%2,%3}, [%4];" \
                 : "=r"(r0), "=r"(r1), "=r"(r2), "=r"(r3) : "r"(addr))

#define MMA_F16(d, a, b0, b1) \
    asm volatile("mma.sync.aligned.m16n8k16.row.col.f32.f16.f16.f32 " \
                 "{%0,%1,%2,%3}, {%4,%5,%6,%7}, {%8,%9}, {%0,%1,%2,%3};" \
                 : "+f"((d)[0]), "+f"((d)[1]), "+f"((d)[2]), "+f"((d)[3]) \
                 : "r"((a)[0]), "r"((a)[1]), "r"((a)[2]), "r"((a)[3]), \
                   "r"(b0), "r"(b1))

__device__ __forceinline__ void cpasync16(uint32_t saddr, const void* g) {
    asm volatile("cp.async.cg.shared.global [%0], [%1], 16;" :: "r"(saddr), "l"(g) : "memory");
}

// ---------------- quantize: fp32 -> fp16 (weights and activations) ----------------
__global__ void __launch_bounds__(256)
cvt_h_kernel(const float* __restrict__ in, unsigned short* __restrict__ outp, int n8)
{
    const int i = blockIdx.x * 256 + threadIdx.x;
    if (i >= n8) return;
    float4 a = ((const float4*)in)[2 * i];
    float4 b = ((const float4*)in)[2 * i + 1];
    ((uint4*)outp)[i] = cvt8h(a, b);
}

// ---------------- HMMA GEMM: C[m,n] = sum_k A[m,k] * W[n,k] (+epilogue) ----------------
// A, W: fp16 in gmem (pre-quantized), pure cp.async 2-slot ring.
// CTA 128x128, 256 threads (8 warps, warp tile 64x32), K-stage 64 -> 2 CTAs/SM.
#define KSTAGE 64
#define NKIT   (DMODEL / KSTAGE)           // 16
#define ROWB   144                         // 128B row + 16B pad: conflict-free ldmatrix
#define SUBT   (128 * ROWB)                // 18432 B: 128x64 fp16 sub-tile (A or B)
#define SLOT   (2 * SUBT)                  // 36864
#define GEMM_SMEM (2 * SLOT)               // 73728

template <int MODE>
__global__ void __launch_bounds__(256, 2)
gemm_h1(const unsigned short* __restrict__ Ah, const unsigned short* __restrict__ Bh,
        float* __restrict__ C, const float* __restrict__ bias)
{
    extern __shared__ char smem[];
    const uint32_t sbase = smem_u32(smem);

    const int tid  = threadIdx.x;
    const int wid  = tid >> 5;
    const int lane = tid & 31;
    const int rowBase = blockIdx.y * 128;
    const int colBase = blockIdx.x * 128;

    const int wm = (wid & 1) * 64;          // 2 warps along M
    const int wn = (wid >> 1) * 32;         // 4 warps along N

    const uint32_t aoff = (uint32_t)(wm + (lane & 15)) * ROWB + (uint32_t)(lane >> 4) * 16;
    const uint32_t boff = (uint32_t)(wn + (lane & 7) + ((lane >> 4) << 3)) * ROWB
                        + (uint32_t)((lane >> 3) & 1) * 16;

    // staging map: A and B each 1024 chunks (128 rows x 8 x 16B), 4/thread
    const unsigned short* gA[4];
    const unsigned short* gB[4];
    uint32_t soa[4], sob[4];
#pragma unroll
    for (int j = 0; j < 4; j++) {
        const int x = tid + 256 * j;
        const int r = x >> 3, c = x & 7;
        gA[j] = Ah + (size_t)(rowBase + r) * DMODEL + c * 8;
        gB[j] = Bh + (size_t)(colBase + r) * DMODEL + c * 8;
        soa[j] = (uint32_t)r * ROWB + (uint32_t)c * 16;
        sob[j] = SUBT + soa[j];
    }

    float acc[4][4][4];
#pragma unroll
    for (int i = 0; i < 4; i++)
#pragma unroll
        for (int j = 0; j < 4; j++)
#pragma unroll
            for (int r = 0; r < 4; r++) acc[i][j][r] = 0.f;

    // ---- prologue: stage 0 ----
#pragma unroll
    for (int j = 0; j < 4; j++) cpasync16(sbase + soa[j], gA[j]);
#pragma unroll
    for (int j = 0; j < 4; j++) cpasync16(sbase + sob[j], gB[j]);
    asm volatile("cp.async.commit_group;" ::: "memory");
    asm volatile("cp.async.wait_group 0;" ::: "memory");
    __syncthreads();

    for (int it = 0; it < NKIT; ++it) {
        const uint32_t slot = sbase + (it & 1) * SLOT;

        // prefetch stage it+1 into the other slot (freed at end of it-1)
        if (it + 1 < NKIT) {
            const int kt = (it + 1) * KSTAGE;
            const uint32_t ns = sbase + ((it + 1) & 1) * SLOT;
#pragma unroll
            for (int j = 0; j < 4; j++) cpasync16(ns + soa[j], gA[j] + kt);
#pragma unroll
            for (int j = 0; j < 4; j++) cpasync16(ns + sob[j], gB[j] + kt);
            asm volatile("cp.async.commit_group;" ::: "memory");
        }

        // ---- compute slot it&1: 4 k16-slices ----
        const uint32_t pA = slot + aoff;
        const uint32_t pB = slot + SUBT + boff;

#pragma unroll
        for (int kk = 0; kk < 4; kk++) {
            const uint32_t ko = (uint32_t)kk * 32;   // 16 fp16 = 32 bytes
            uint32_t ah[16], bb[8];
            LDSM_X4(ah[0],  ah[1],  ah[2],  ah[3],  pA + ko);
            LDSM_X4(ah[4],  ah[5],  ah[6],  ah[7],  pA + 16 * ROWB + ko);
            LDSM_X4(ah[8],  ah[9],  ah[10], ah[11], pA + 32 * ROWB + ko);
            LDSM_X4(ah[12], ah[13], ah[14], ah[15], pA + 48 * ROWB + ko);
            LDSM_X4(bb[0], bb[1], bb[2], bb[3], pB + ko);
            LDSM_X4(bb[4], bb[5], bb[6], bb[7], pB + 16 * ROWB + ko);
#pragma unroll
            for (int mt = 0; mt < 4; mt++)
#pragma unroll
                for (int j = 0; j < 4; j++)
                    MMA_F16(acc[mt][j], ah + mt * 4, bb[j * 2], bb[j * 2 + 1]);
        }

        if (it + 1 < NKIT)
            asm volatile("cp.async.wait_group 0;" ::: "memory");
        __syncthreads();
    }

    // ---- epilogue ----
    const int lrow = lane >> 2;
    const int lcol = (lane & 3) * 2;
#pragma unroll
    for (int mt = 0; mt < 4; mt++) {
#pragma unroll
        for (int j = 0; j < 4; j++) {
            const int col = colBase + wn + j * 8 + lcol;
#pragma unroll
            for (int half = 0; half < 2; half++) {
                const int row = rowBase + wm + mt * 16 + lrow + half * 8;
                float v0 = acc[mt][j][half * 2 + 0];
                float v1 = acc[mt][j][half * 2 + 1];
                if (MODE == 1) {
                    v0 = (v0 > 0.f) ? (v0 + 1.f) : __expf(v0);
                    v1 = (v1 > 0.f) ? (v1 + 1.f) : __expf(v1);
                } else if (MODE == 2) {
                    v0 += bias[col];
                    v1 += bias[col + 1];
                }
                *(float2*)(C + (size_t)row * DMODEL + col) = make_float2(v0, v1);
            }
        }
    }
}

// ---------------- KV partial: per (bh, chunk) sum_s K^T V over SEQ/NCH s ----------------
__global__ void __launch_bounds__(256)
kv_partial_kernel()
{
    const int bh = blockIdx.x;
    const int ch = blockIdx.y;
    const int b = bh >> 4, h = bh & 15;
    const int tid = threadIdx.x;

    __shared__ float Ksh[16][DK];
    __shared__ float Vsh[16][DK];

    const int e = tid & 63;
    const int dbase = (tid >> 6) * 16;

    unsigned long long acc[8];
    {
        const unsigned long long z = pack2(0.f, 0.f);
#pragma unroll
        for (int i = 0; i < 8; i++) acc[i] = z;
    }
    float ksum = 0.f;

    const int s0 = ch * (SEQ / NCH);
    const size_t base = ((size_t)b * SEQ + s0) * DMODEL + h * DK;
    const int lr = tid >> 4;
    const int lc = (tid & 15) * 4;

    for (int st = 0; st < SEQ / NCH; st += 16) {
        const size_t g = base + (size_t)(st + lr) * DMODEL + lc;
        *(float4*)&Ksh[lr][lc] = *(const float4*)(g_K + g);
        *(float4*)&Vsh[lr][lc] = *(const float4*)(g_V + g);
        __syncthreads();

#pragma unroll
        for (int r = 0; r < 16; r++) {
            const float vv = Vsh[r][e];
            const unsigned long long vvp = pack2(vv, vv);
            const ulonglong2 kA = *(const ulonglong2*)&Ksh[r][dbase];
            const ulonglong2 kB = *(const ulonglong2*)&Ksh[r][dbase + 4];
            const ulonglong2 kC = *(const ulonglong2*)&Ksh[r][dbase + 8];
            const ulonglong2 kD = *(const ulonglong2*)&Ksh[r][dbase + 12];
            ffma2(acc[0], kA.x, vvp); ffma2(acc[1], kA.y, vvp);
            ffma2(acc[2], kB.x, vvp); ffma2(acc[3], kB.y, vvp);
            ffma2(acc[4], kC.x, vvp); ffma2(acc[5], kC.y, vvp);
            ffma2(acc[6], kD.x, vvp); ffma2(acc[7], kD.y, vvp);
        }
        if (tid < 64) {
#pragma unroll
            for (int r = 0; r < 16; r++) ksum += Ksh[r][tid];
        }
        __syncthreads();
    }

    float* pkv = g_pKV + ((size_t)ch * BH + bh) * (DK * DK);
#pragma unroll
    for (int p = 0; p < 8; p++) {
        float v0, v1;
        unpack2(acc[p], v0, v1);
        pkv[(dbase + 2 * p) * DK + e] = v0;
        pkv[(dbase + 2 * p + 1) * DK + e] = v1;
    }
    if (tid < 64) g_pKsum[((size_t)ch * BH + bh) * DK + tid] = ksum;
}

// ---------------- KV reduce ----------------
__global__ void kv_reduce_kernel()
{
    const int idx = blockIdx.x * 256 + threadIdx.x;
    const int NKV = BH * DK * DK;
    if (idx < NKV) {
        float s = 0.f;
#pragma unroll
        for (int ch = 0; ch < NCH; ch++) s += g_pKV[(size_t)ch * NKV + idx];
        g_KV[idx] = s;
    } else if (idx < NKV + BH * DK) {
        const int o = idx - NKV;
        float s = 0.f;
#pragma unroll
        for (int ch = 0; ch < NCH; ch++) s += g_pKsum[(size_t)ch * BH * DK + o];
        g_Ksum[o] = s;
    }
}

// ---------------- attention apply: out = (Q @ KV) / (Q . Ksum + eps) -> fp16 ----------------
__global__ void __launch_bounds__(256)
attn_kernel()
{
    const int bh = blockIdx.x;
    const int qt = blockIdx.y;
    const int b = bh >> 4, h = bh & 15;
    const int tid = threadIdx.x;

    __shared__ float KVs[DK * DK];
    __shared__ float Qs[DK][DK + 2];
    __shared__ float Ksm[DK];
    __shared__ float rden[DK];

    const size_t base = ((size_t)b * SEQ + qt * DK) * DMODEL + h * DK;

#pragma unroll
    for (int l = 0; l < 16; l++) {
        const int idx = tid + l * 256;
        KVs[idx] = g_KV[(size_t)bh * DK * DK + idx];
        const int q = idx >> 6, d = idx & 63;
        Qs[d][q] = g_Q[base + (size_t)q * DMODEL + d];
    }
    if (tid < DK) Ksm[tid] = g_Ksum[bh * DK + tid];
    __syncthreads();

    if (tid < DK) {
        float s = 0.f;
#pragma unroll
        for (int d = 0; d < DK; d++) s += Qs[d][tid] * Ksm[d];
        rden[tid] = 1.f / (s + 1e-6f);
    }
    __syncthreads();

    const int e = tid & 63;
    const int qg = tid >> 6;

    unsigned long long acc[8];
    {
        const unsigned long long z = pack2(0.f, 0.f);
#pragma unroll
        for (int i = 0; i < 8; i++) acc[i] = z;
    }

#pragma unroll 8
    for (int d = 0; d < DK; d++) {
        const float kv = KVs[d * DK + e];
        const unsigned long long kvp = pack2(kv, kv);
#pragma unroll
        for (int t = 0; t < 8; t++) {
            const unsigned long long qp =
                *(const unsigned long long*)&Qs[d][qg * 16 + 2 * t];
            ffma2(acc[t], qp, kvp);
        }
    }

#pragma unroll
    for (int t = 0; t < 8; t++) {
        float v0, v1;
        unpack2(acc[t], v0, v1);
        const int q0 = qg * 16 + 2 * t;
        v0 *= rden[q0];
        v1 *= rden[q0 + 1];
        unsigned short h0, h1;
        asm("cvt.rn.f16.f32 %0, %1;" : "=h"(h0) : "f"(v0));
        asm("cvt.rn.f16.f32 %0, %1;" : "=h"(h1) : "f"(v1));
        g_af16[base + (size_t)q0 * DMODEL + e] = h0;
        g_af16[base + (size_t)(q0 + 1) * DMODEL + e] = h1;
    }
}

// ---------------- launch ----------------
extern "C" void kernel_launch(void* const* d_in, const int* in_sizes, int n_in,
                              void* d_out, int out_size)
{
    const float* query = (const float*)d_in[0];
    const float* key   = (const float*)d_in[1];
    const float* value = (const float*)d_in[2];
    const float* Wq    = (const float*)d_in[3];
    const float* Wk    = (const float*)d_in[4];
    const float* Wv    = (const float*)d_in[5];
    const float* Wo    = (const float*)d_in[6];
    const float* bo    = (const float*)d_in[7];
    float* out = (float*)d_out;
    (void)in_sizes; (void)n_in; (void)out_size;

    float *pQ, *pK, *pV;
    unsigned short *xh, *wh, *af16;
    cudaGetSymbolAddress((void**)&pQ, g_Q);
    cudaGetSymbolAddress((void**)&pK, g_K);
    cudaGetSymbolAddress((void**)&pV, g_V);
    cudaGetSymbolAddress((void**)&xh, g_xh);
    cudaGetSymbolAddress((void**)&wh, g_wh);
    cudaGetSymbolAddress((void**)&af16, g_af16);

    cudaFuncSetAttribute(gemm_h1<0>, cudaFuncAttributeMaxDynamicSharedMemorySize, GEMM_SMEM);
    cudaFuncSetAttribute(gemm_h1<1>, cudaFuncAttributeMaxDynamicSharedMemorySize, GEMM_SMEM);
    cudaFuncSetAttribute(gemm_h1<2>, cudaFuncAttributeMaxDynamicSharedMemorySize, GEMM_SMEM);

    const int n8w = DMODEL * DMODEL / 8;
    const int n8a = M_TOTAL * DMODEL / 8;
    const int cb = 256;
    const dim3 ggrid(DMODEL / 128, M_TOTAL / 128);   // (8, 128) = 1024 CTAs

    // Q = phi(query @ Wq^T)
    cvt_h_kernel<<<(n8a + cb - 1) / cb, cb>>>(query, xh, n8a);
    cvt_h_kernel<<<(n8w + cb - 1) / cb, cb>>>(Wq, wh, n8w);
    gemm_h1<1><<<ggrid, 256, GEMM_SMEM>>>(xh, wh, pQ, nullptr);

    // K = phi(key @ Wk^T)
    cvt_h_kernel<<<(n8a + cb - 1) / cb, cb>>>(key, xh, n8a);
    cvt_h_kernel<<<(n8w + cb - 1) / cb, cb>>>(Wk, wh, n8w);
    gemm_h1<1><<<ggrid, 256, GEMM_SMEM>>>(xh, wh, pK, nullptr);

    // V = value @ Wv^T
    cvt_h_kernel<<<(n8a + cb - 1) / cb, cb>>>(value, xh, n8a);
    cvt_h_kernel<<<(n8w + cb - 1) / cb, cb>>>(Wv, wh, n8w);
    gemm_h1<0><<<ggrid, 256, GEMM_SMEM>>>(xh, wh, pV, nullptr);

    // linear attention core
    kv_partial_kernel<<<dim3(BH, NCH), 256>>>();
    kv_reduce_kernel<<<(BH * DK * DK + BH * DK + 255) / 256, 256>>>();
    attn_kernel<<<dim3(BH, SEQ / DK), 256>>>();

    // out = attn @ Wo^T + bo  (A pre-quantized fp16 by attn_kernel)
    cvt_h_kernel<<<(n8w + cb - 1) / cb, cb>>>(Wo, wh, n8w);
    gemm_h1<2><<<ggrid, 256, GEMM_SMEM>>>(af16, wh, out, bo);
}

// round 14
// speedup vs baseline: 2.0708x; 1.0396x over previous
#include <cuda_runtime.h>
#include <cuda_fp16.h>
#include <cstdint>
#include <cstddef>

// Problem constants
#define DMODEL 1024
#define SEQ    4096
#define BATCH  4
#define NHEAD  16
#define DK     64
#define M_TOTAL (BATCH * SEQ)   // 16384
#define BH      (BATCH * NHEAD) // 64
#define NCH     16
#define AD      ((size_t)M_TOTAL * DMODEL)
#define WD      ((size_t)DMODEL * DMODEL)

// ---------------- scratch (static device globals; no allocation) ----------------
__device__ unsigned short g_xh3[3 * AD];    // fp16 query|key|value
__device__ unsigned short g_qkv[3 * AD];    // fp16 Q|K|V (phi applied to Q,K)
__device__ unsigned short g_af16[AD];       // attn output, fp16
__device__ unsigned short g_wh[4 * WD];     // fp16 Wq|Wk|Wv|Wo
__device__ float g_pKV[(size_t)NCH * BH * DK * DK];
__device__ float g_pKsum[(size_t)NCH * BH * DK];
__device__ float g_KV[(size_t)BH * DK * DK];
__device__ float g_Ksum[(size_t)BH * DK];

// ---------------- helpers ----------------
__device__ __forceinline__ unsigned long long pack2(float x, float y) {
    unsigned long long r;
    asm("mov.b64 %0, {%1, %2};" : "=l"(r) : "f"(x), "f"(y));
    return r;
}
__device__ __forceinline__ void unpack2(unsigned long long v, float& x, float& y) {
    asm("mov.b64 {%0, %1}, %2;" : "=f"(x), "=f"(y) : "l"(v));
}
__device__ __forceinline__ void ffma2(unsigned long long& d,
                                      unsigned long long a,
                                      unsigned long long b) {
    asm("fma.rn.f32x2 %0, %1, %2, %0;" : "+l"(d) : "l"(a), "l"(b));
}
__device__ __forceinline__ uint32_t smem_u32(const void* p) {
    uint32_t a;
    asm("{ .reg .u64 t; cvta.to.shared.u64 t, %1; cvt.u32.u64 %0, t; }" : "=r"(a) : "l"(p));
    return a;
}
__device__ __forceinline__ uint32_t cvt_h2(float hi_val, float lo_val) {
    uint32_t r;
    asm("cvt.rn.f16x2.f32 %0, %1, %2;" : "=r"(r) : "f"(hi_val), "f"(lo_val));
    return r;   // low half = lo_val, high half = hi_val
}
__device__ __forceinline__ uint4 cvt8h(const float4& a, const float4& b) {
    uint4 r;
    r.x = cvt_h2(a.y, a.x);
    r.y = cvt_h2(a.w, a.z);
    r.z = cvt_h2(b.y, b.x);
    r.w = cvt_h2(b.w, b.z);
    return r;
}
__device__ __forceinline__ float2 h2f2(uint32_t h) {
    float2 r;
    asm("{ .reg .f16 a, b;\n\t mov.b32 {a, b}, %2;\n\t"
        " cvt.f32.f16 %0, a;\n\t cvt.f32.f16 %1, b; }"
        : "=f"(r.x), "=f"(r.y) : "r"(h));
    return r;
}

#define LDSM_X4(r0, r1, r2, r3, addr) \
    asm volatile("ldmatrix.sync.aligned.m8n8.x4.shared.b16 {%0,%1,%2,%3}, [%4];" \
                 : "=r"(r0), "=r"(r1), "=r"(r2), "=r"(r3) : "r"(addr))

#define MMA_F16(d, a, b0, b1) \
    asm volatile("mma.sync.aligned.m16n8k16.row.col.f32.f16.f16.f32 " \
                 "{%0,%1,%2,%3}, {%4,%5,%6,%7}, {%8,%9}, {%0,%1,%2,%3};" \
                 : "+f"((d)[0]), "+f"((d)[1]), "+f"((d)[2]), "+f"((d)[3]) \
                 : "r"((a)[0]), "r"((a)[1]), "r"((a)[2]), "r"((a)[3]), \
                   "r"(b0), "r"(b1))

__device__ __forceinline__ void cpasync16(uint32_t saddr, const void* g) {
    asm volatile("cp.async.cg.shared.global [%0], [%1], 16;" :: "r"(saddr), "l"(g) : "memory");
}

// ---------------- batched quantize: fp32 -> fp16, up to 4 sources ----------------
__global__ void __launch_bounds__(256)
cvt_batch_kernel(const float* __restrict__ s0, const float* __restrict__ s1,
                 const float* __restrict__ s2, const float* __restrict__ s3,
                 unsigned short* __restrict__ dst, size_t perN8, int n8)
{
    const int i = blockIdx.x * 256 + threadIdx.x;
    if (i >= n8) return;
    const float* srcs[4] = {s0, s1, s2, s3};
    const float* in = srcs[blockIdx.y];
    unsigned short* outp = dst + blockIdx.y * perN8 * 8;
    float4 a = ((const float4*)in)[2 * i];
    float4 b = ((const float4*)in)[2 * i + 1];
    ((uint4*)outp)[i] = cvt8h(a, b);
}

// ---------------- HMMA GEMM: C[m,n] = sum_k A[m,k] * W[n,k] (+epilogue) ----------------
// A, W: fp16 in gmem, pure cp.async 2-slot ring.
// CTA 128x128, 256 threads (8 warps, warp tile 64x32), K-stage 64 -> 2 CTAs/SM.
// blockIdx.z batches independent GEMMs (A/B/C strided by AD/WD/AD).
// OUTHALF=1: fp16 C, mode = z==2 ? none : phi.  OUTHALF=0: fp32 C + bias.
#define KSTAGE 64
#define NKIT   (DMODEL / KSTAGE)           // 16
#define ROWB   144                         // 128B row + 16B pad: conflict-free ldmatrix
#define SUBT   (128 * ROWB)                // 18432 B: 128x64 fp16 sub-tile (A or B)
#define SLOT   (2 * SUBT)                  // 36864
#define GEMM_SMEM (2 * SLOT)               // 73728

template <int OUTHALF>
__global__ void __launch_bounds__(256, 2)
gemm_h1(const unsigned short* __restrict__ Ah0, const unsigned short* __restrict__ Bh0,
        void* __restrict__ Cv, const float* __restrict__ bias)
{
    extern __shared__ char smem[];
    const uint32_t sbase = smem_u32(smem);

    const int tid  = threadIdx.x;
    const int wid  = tid >> 5;
    const int lane = tid & 31;
    const int rowBase = blockIdx.y * 128;
    const int colBase = blockIdx.x * 128;
    const int z = blockIdx.z;

    const unsigned short* Ah = Ah0 + (size_t)z * AD;
    const unsigned short* Bh = Bh0 + (size_t)z * WD;

    const int wm = (wid & 1) * 64;          // 2 warps along M
    const int wn = (wid >> 1) * 32;         // 4 warps along N

    const uint32_t aoff = (uint32_t)(wm + (lane & 15)) * ROWB + (uint32_t)(lane >> 4) * 16;
    const uint32_t boff = (uint32_t)(wn + (lane & 7) + ((lane >> 4) << 3)) * ROWB
                        + (uint32_t)((lane >> 3) & 1) * 16;

    // staging map: A and B each 1024 chunks (128 rows x 8 x 16B), 4/thread
    const unsigned short* gA[4];
    const unsigned short* gB[4];
    uint32_t soa[4], sob[4];
#pragma unroll
    for (int j = 0; j < 4; j++) {
        const int x = tid + 256 * j;
        const int r = x >> 3, c = x & 7;
        gA[j] = Ah + (size_t)(rowBase + r) * DMODEL + c * 8;
        gB[j] = Bh + (size_t)(colBase + r) * DMODEL + c * 8;
        soa[j] = (uint32_t)r * ROWB + (uint32_t)c * 16;
        sob[j] = SUBT + soa[j];
    }

    float acc[4][4][4];
#pragma unroll
    for (int i = 0; i < 4; i++)
#pragma unroll
        for (int j = 0; j < 4; j++)
#pragma unroll
            for (int r = 0; r < 4; r++) acc[i][j][r] = 0.f;

    // ---- prologue: stage 0 ----
#pragma unroll
    for (int j = 0; j < 4; j++) cpasync16(sbase + soa[j], gA[j]);
#pragma unroll
    for (int j = 0; j < 4; j++) cpasync16(sbase + sob[j], gB[j]);
    asm volatile("cp.async.commit_group;" ::: "memory");
    asm volatile("cp.async.wait_group 0;" ::: "memory");
    __syncthreads();

    for (int it = 0; it < NKIT; ++it) {
        const uint32_t slot = sbase + (it & 1) * SLOT;

        if (it + 1 < NKIT) {
            const int kt = (it + 1) * KSTAGE;
            const uint32_t ns = sbase + ((it + 1) & 1) * SLOT;
#pragma unroll
            for (int j = 0; j < 4; j++) cpasync16(ns + soa[j], gA[j] + kt);
#pragma unroll
            for (int j = 0; j < 4; j++) cpasync16(ns + sob[j], gB[j] + kt);
            asm volatile("cp.async.commit_group;" ::: "memory");
        }

        const uint32_t pA = slot + aoff;
        const uint32_t pB = slot + SUBT + boff;

#pragma unroll
        for (int kk = 0; kk < 4; kk++) {
            const uint32_t ko = (uint32_t)kk * 32;   // 16 fp16 = 32 bytes
            uint32_t ah[16], bb[8];
            LDSM_X4(ah[0],  ah[1],  ah[2],  ah[3],  pA + ko);
            LDSM_X4(ah[4],  ah[5],  ah[6],  ah[7],  pA + 16 * ROWB + ko);
            LDSM_X4(ah[8],  ah[9],  ah[10], ah[11], pA + 32 * ROWB + ko);
            LDSM_X4(ah[12], ah[13], ah[14], ah[15], pA + 48 * ROWB + ko);
            LDSM_X4(bb[0], bb[1], bb[2], bb[3], pB + ko);
            LDSM_X4(bb[4], bb[5], bb[6], bb[7], pB + 16 * ROWB + ko);
#pragma unroll
            for (int mt = 0; mt < 4; mt++)
#pragma unroll
                for (int j = 0; j < 4; j++)
                    MMA_F16(acc[mt][j], ah + mt * 4, bb[j * 2], bb[j * 2 + 1]);
        }

        if (it + 1 < NKIT)
            asm volatile("cp.async.wait_group 0;" ::: "memory");
        __syncthreads();
    }

    // ---- epilogue ----
    const int lrow = lane >> 2;
    const int lcol = (lane & 3) * 2;
    const int phi = OUTHALF ? (z != 2) : 0;
#pragma unroll
    for (int mt = 0; mt < 4; mt++) {
#pragma unroll
        for (int j = 0; j < 4; j++) {
            const int col = colBase + wn + j * 8 + lcol;
#pragma unroll
            for (int half = 0; half < 2; half++) {
                const int row = rowBase + wm + mt * 16 + lrow + half * 8;
                float v0 = acc[mt][j][half * 2 + 0];
                float v1 = acc[mt][j][half * 2 + 1];
                if (OUTHALF) {
                    if (phi) {
                        v0 = (v0 > 0.f) ? (v0 + 1.f) : __expf(v0);
                        v1 = (v1 > 0.f) ? (v1 + 1.f) : __expf(v1);
                    }
                    unsigned short* Ch = (unsigned short*)Cv + (size_t)z * AD;
                    *(uint32_t*)(Ch + (size_t)row * DMODEL + col) = cvt_h2(v1, v0);
                } else {
                    v0 += bias[col];
                    v1 += bias[col + 1];
                    *(float2*)((float*)Cv + (size_t)row * DMODEL + col) = make_float2(v0, v1);
                }
            }
        }
    }
}

// ---------------- KV partial: per (bh, chunk) sum_s K^T V over SEQ/NCH s ----------------
__global__ void __launch_bounds__(256)
kv_partial_kernel()
{
    const int bh = blockIdx.x;
    const int ch = blockIdx.y;
    const int b = bh >> 4, h = bh & 15;
    const int tid = threadIdx.x;

    __shared__ float Ksh[16][DK];
    __shared__ float Vsh[16][DK];

    const int e = tid & 63;
    const int dbase = (tid >> 6) * 16;

    unsigned long long acc[8];
    {
        const unsigned long long z = pack2(0.f, 0.f);
#pragma unroll
        for (int i = 0; i < 8; i++) acc[i] = z;
    }
    float ksum = 0.f;

    const int s0 = ch * (SEQ / NCH);
    const size_t base = ((size_t)b * SEQ + s0) * DMODEL + h * DK;
    const int lr = tid >> 4;
    const int lc = (tid & 15) * 4;
    const unsigned short* gK = g_qkv + AD;        // K slice
    const unsigned short* gV = g_qkv + 2 * AD;    // V slice

    for (int st = 0; st < SEQ / NCH; st += 16) {
        const size_t g = base + (size_t)(st + lr) * DMODEL + lc;
        const uint2 kp = *(const uint2*)(gK + g);
        const uint2 vp = *(const uint2*)(gV + g);
        const float2 k0 = h2f2(kp.x), k1 = h2f2(kp.y);
        const float2 v0 = h2f2(vp.x), v1 = h2f2(vp.y);
        *(float4*)&Ksh[lr][lc] = make_float4(k0.x, k0.y, k1.x, k1.y);
        *(float4*)&Vsh[lr][lc] = make_float4(v0.x, v0.y, v1.x, v1.y);
        __syncthreads();

#pragma unroll
        for (int r = 0; r < 16; r++) {
            const float vv = Vsh[r][e];
            const unsigned long long vvp = pack2(vv, vv);
            const ulonglong2 kA = *(const ulonglong2*)&Ksh[r][dbase];
            const ulonglong2 kB = *(const ulonglong2*)&Ksh[r][dbase + 4];
            const ulonglong2 kC = *(const ulonglong2*)&Ksh[r][dbase + 8];
            const ulonglong2 kD = *(const ulonglong2*)&Ksh[r][dbase + 12];
            ffma2(acc[0], kA.x, vvp); ffma2(acc[1], kA.y, vvp);
            ffma2(acc[2], kB.x, vvp); ffma2(acc[3], kB.y, vvp);
            ffma2(acc[4], kC.x, vvp); ffma2(acc[5], kC.y, vvp);
            ffma2(acc[6], kD.x, vvp); ffma2(acc[7], kD.y, vvp);
        }
        if (tid < 64) {
#pragma unroll
            for (int r = 0; r < 16; r++) ksum += Ksh[r][tid];
        }
        __syncthreads();
    }

    float* pkv = g_pKV + ((size_t)ch * BH + bh) * (DK * DK);
#pragma unroll
    for (int p = 0; p < 8; p++) {
        float v0, v1;
        unpack2(acc[p], v0, v1);
        pkv[(dbase + 2 * p) * DK + e] = v0;
        pkv[(dbase + 2 * p + 1) * DK + e] = v1;
    }
    if (tid < 64) g_pKsum[((size_t)ch * BH + bh) * DK + tid] = ksum;
}

// ---------------- KV reduce ----------------
__global__ void kv_reduce_kernel()
{
    const int idx = blockIdx.x * 256 + threadIdx.x;
    const int NKV = BH * DK * DK;
    if (idx < NKV) {
        float s = 0.f;
#pragma unroll
        for (int ch = 0; ch < NCH; ch++) s += g_pKV[(size_t)ch * NKV + idx];
        g_KV[idx] = s;
    } else if (idx < NKV + BH * DK) {
        const int o = idx - NKV;
        float s = 0.f;
#pragma unroll
        for (int ch = 0; ch < NCH; ch++) s += g_pKsum[(size_t)ch * BH * DK + o];
        g_Ksum[o] = s;
    }
}

// ---------------- attention apply: out = (Q @ KV) / (Q . Ksum + eps) -> fp16 ----------------
__global__ void __launch_bounds__(256)
attn_kernel()
{
    const int bh = blockIdx.x;
    const int qt = blockIdx.y;
    const int b = bh >> 4, h = bh & 15;
    const int tid = threadIdx.x;

    __shared__ float KVs[DK * DK];
    __shared__ float Qs[DK][DK + 2];
    __shared__ float Ksm[DK];
    __shared__ float rden[DK];

    const size_t base = ((size_t)b * SEQ + qt * DK) * DMODEL + h * DK;
    const unsigned short* gQ = g_qkv;   // Q slice

#pragma unroll
    for (int l = 0; l < 16; l++) {
        const int idx = tid + l * 256;
        KVs[idx] = g_KV[(size_t)bh * DK * DK + idx];
        const int q = idx >> 6, d = idx & 63;
        Qs[d][q] = __half2float(((const __half*)gQ)[base + (size_t)q * DMODEL + d]);
    }
    if (tid < DK) Ksm[tid] = g_Ksum[bh * DK + tid];
    __syncthreads();

    if (tid < DK) {
        float s = 0.f;
#pragma unroll
        for (int d = 0; d < DK; d++) s += Qs[d][tid] * Ksm[d];
        rden[tid] = 1.f / (s + 1e-6f);
    }
    __syncthreads();

    const int e = tid & 63;
    const int qg = tid >> 6;

    unsigned long long acc[8];
    {
        const unsigned long long z = pack2(0.f, 0.f);
#pragma unroll
        for (int i = 0; i < 8; i++) acc[i] = z;
    }

#pragma unroll 8
    for (int d = 0; d < DK; d++) {
        const float kv = KVs[d * DK + e];
        const unsigned long long kvp = pack2(kv, kv);
#pragma unroll
        for (int t = 0; t < 8; t++) {
            const unsigned long long qp =
                *(const unsigned long long*)&Qs[d][qg * 16 + 2 * t];
            ffma2(acc[t], qp, kvp);
        }
    }

#pragma unroll
    for (int t = 0; t < 8; t++) {
        float v0, v1;
        unpack2(acc[t], v0, v1);
        const int q0 = qg * 16 + 2 * t;
        v0 *= rden[q0];
        v1 *= rden[q0 + 1];
        unsigned short h0, h1;
        asm("cvt.rn.f16.f32 %0, %1;" : "=h"(h0) : "f"(v0));
        asm("cvt.rn.f16.f32 %0, %1;" : "=h"(h1) : "f"(v1));
        g_af16[base + (size_t)q0 * DMODEL + e] = h0;
        g_af16[base + (size_t)(q0 + 1) * DMODEL + e] = h1;
    }
}

// ---------------- launch ----------------
extern "C" void kernel_launch(void* const* d_in, const int* in_sizes, int n_in,
                              void* d_out, int out_size)
{
    const float* query = (const float*)d_in[0];
    const float* key   = (const float*)d_in[1];
    const float* value = (const float*)d_in[2];
    const float* Wq    = (const float*)d_in[3];
    const float* Wk    = (const float*)d_in[4];
    const float* Wv    = (const float*)d_in[5];
    const float* Wo    = (const float*)d_in[6];
    const float* bo    = (const float*)d_in[7];
    float* out = (float*)d_out;
    (void)in_sizes; (void)n_in; (void)out_size;

    unsigned short *xh3, *qkv, *wh, *af16;
    cudaGetSymbolAddress((void**)&xh3, g_xh3);
    cudaGetSymbolAddress((void**)&qkv, g_qkv);
    cudaGetSymbolAddress((void**)&wh, g_wh);
    cudaGetSymbolAddress((void**)&af16, g_af16);

    cudaFuncSetAttribute(gemm_h1<0>, cudaFuncAttributeMaxDynamicSharedMemorySize, GEMM_SMEM);
    cudaFuncSetAttribute(gemm_h1<1>, cudaFuncAttributeMaxDynamicSharedMemorySize, GEMM_SMEM);

    const int n8w = (int)(WD / 8);
    const int n8a = (int)(AD / 8);
    const int cb = 256;

    // quantize: all 4 weights (one launch), all 3 activations (one launch)
    cvt_batch_kernel<<<dim3((n8w + cb - 1) / cb, 4), cb>>>(Wq, Wk, Wv, Wo, wh, WD / 8, n8w);
    cvt_batch_kernel<<<dim3((n8a + cb - 1) / cb, 3), cb>>>(query, key, value, nullptr,
                                                           xh3, AD / 8, n8a);

    // batched QKV projections: z=0 Q(phi), z=1 K(phi), z=2 V
    gemm_h1<1><<<dim3(DMODEL / 128, M_TOTAL / 128, 3), 256, GEMM_SMEM>>>(xh3, wh, qkv, nullptr);

    // linear attention core
    kv_partial_kernel<<<dim3(BH, NCH), 256>>>();
    kv_reduce_kernel<<<(BH * DK * DK + BH * DK + 255) / 256, 256>>>();
    attn_kernel<<<dim3(BH, SEQ / DK), 256>>>();

    // out = attn @ Wo^T + bo
    gemm_h1<0><<<dim3(DMODEL / 128, M_TOTAL / 128, 1), 256, GEMM_SMEM>>>(af16, wh + 3 * WD,
                                                                         out, bo);
}

// round 15
// speedup vs baseline: 2.3199x; 1.1203x over previous
#include <cuda_runtime.h>
#include <cuda_fp16.h>
#include <cstdint>
#include <cstddef>

// Problem constants
#define DMODEL 1024
#define SEQ    4096
#define BATCH  4
#define NHEAD  16
#define DK     64
#define M_TOTAL (BATCH * SEQ)   // 16384
#define BH      (BATCH * NHEAD) // 64
#define NCH     8
#define AD      ((size_t)M_TOTAL * DMODEL)
#define WD      ((size_t)DMODEL * DMODEL)

// ---------------- scratch (static device globals; no allocation) ----------------
__device__ unsigned short g_xh3[3 * AD];    // fp16 query|key|value
__device__ unsigned short g_qkv[3 * AD];    // fp16 Q|K|V (phi applied to Q,K)
__device__ unsigned short g_af16[AD];       // attn output, fp16
__device__ unsigned short g_wh[4 * WD];     // fp16 Wq|Wk|Wv|Wo
__device__ float g_pKV[(size_t)NCH * BH * DK * DK];
__device__ float g_pKsum[(size_t)NCH * BH * DK];
__device__ float g_KV[(size_t)BH * DK * DK];
__device__ float g_Ksum[(size_t)BH * DK];

// ---------------- helpers ----------------
__device__ __forceinline__ unsigned long long pack2(float x, float y) {
    unsigned long long r;
    asm("mov.b64 %0, {%1, %2};" : "=l"(r) : "f"(x), "f"(y));
    return r;
}
__device__ __forceinline__ void unpack2(unsigned long long v, float& x, float& y) {
    asm("mov.b64 {%0, %1}, %2;" : "=f"(x), "=f"(y) : "l"(v));
}
__device__ __forceinline__ void ffma2(unsigned long long& d,
                                      unsigned long long a,
                                      unsigned long long b) {
    asm("fma.rn.f32x2 %0, %1, %2, %0;" : "+l"(d) : "l"(a), "l"(b));
}
__device__ __forceinline__ uint32_t smem_u32(const void* p) {
    uint32_t a;
    asm("{ .reg .u64 t; cvta.to.shared.u64 t, %1; cvt.u32.u64 %0, t; }" : "=r"(a) : "l"(p));
    return a;
}
__device__ __forceinline__ uint32_t cvt_h2(float hi_val, float lo_val) {
    uint32_t r;
    asm("cvt.rn.f16x2.f32 %0, %1, %2;" : "=r"(r) : "f"(hi_val), "f"(lo_val));
    return r;   // low half = lo_val, high half = hi_val
}
__device__ __forceinline__ uint4 cvt8h(const float4& a, const float4& b) {
    uint4 r;
    r.x = cvt_h2(a.y, a.x);
    r.y = cvt_h2(a.w, a.z);
    r.z = cvt_h2(b.y, b.x);
    r.w = cvt_h2(b.w, b.z);
    return r;
}

#define LDSM_X4(r0, r1, r2, r3, addr) \
    asm volatile("ldmatrix.sync.aligned.m8n8.x4.shared.b16 {%0,%1,%2,%3}, [%4];" \
                 : "=r"(r0), "=r"(r1), "=r"(r2), "=r"(r3) : "r"(addr))

#define LDSM_X4_T(r0, r1, r2, r3, addr) \
    asm volatile("ldmatrix.sync.aligned.m8n8.x4.trans.shared.b16 {%0,%1,%2,%3}, [%4];" \
                 : "=r"(r0), "=r"(r1), "=r"(r2), "=r"(r3) : "r"(addr))

#define MMA_F16(d, a, b0, b1) \
    asm volatile("mma.sync.aligned.m16n8k16.row.col.f32.f16.f16.f32 " \
                 "{%0,%1,%2,%3}, {%4,%5,%6,%7}, {%8,%9}, {%0,%1,%2,%3};" \
                 : "+f"((d)[0]), "+f"((d)[1]), "+f"((d)[2]), "+f"((d)[3]) \
                 : "r"((a)[0]), "r"((a)[1]), "r"((a)[2]), "r"((a)[3]), \
                   "r"(b0), "r"(b1))

__device__ __forceinline__ void cpasync16(uint32_t saddr, const void* g) {
    asm volatile("cp.async.cg.shared.global [%0], [%1], 16;" :: "r"(saddr), "l"(g) : "memory");
}

// ---------------- batched quantize: fp32 -> fp16, up to 4 sources ----------------
__global__ void __launch_bounds__(256)
cvt_batch_kernel(const float* __restrict__ s0, const float* __restrict__ s1,
                 const float* __restrict__ s2, const float* __restrict__ s3,
                 unsigned short* __restrict__ dst, size_t perN8, int n8)
{
    const int i = blockIdx.x * 256 + threadIdx.x;
    if (i >= n8) return;
    const float* srcs[4] = {s0, s1, s2, s3};
    const float* in = srcs[blockIdx.y];
    unsigned short* outp = dst + blockIdx.y * perN8 * 8;
    float4 a = ((const float4*)in)[2 * i];
    float4 b = ((const float4*)in)[2 * i + 1];
    ((uint4*)outp)[i] = cvt8h(a, b);
}

// ---------------- HMMA GEMM: C[m,n] = sum_k A[m,k] * W[n,k] (+epilogue) ----------------
// CTA 128x128, 256 threads (8 warps, warp tile 64x32), K-stage 64 -> 2 CTAs/SM.
// blockIdx.z batches GEMMs. OUTHALF=1: fp16 C, phi unless z==2. OUTHALF=0: fp32 C + bias.
#define KSTAGE 64
#define NKIT   (DMODEL / KSTAGE)           // 16
#define ROWB   144                         // 128B row + 16B pad: conflict-free ldmatrix
#define SUBT   (128 * ROWB)                // 18432 B: 128x64 fp16 sub-tile (A or B)
#define SLOT   (2 * SUBT)                  // 36864
#define GEMM_SMEM (2 * SLOT)               // 73728

template <int OUTHALF>
__global__ void __launch_bounds__(256, 2)
gemm_h1(const unsigned short* __restrict__ Ah0, const unsigned short* __restrict__ Bh0,
        void* __restrict__ Cv, const float* __restrict__ bias)
{
    extern __shared__ char smem[];
    const uint32_t sbase = smem_u32(smem);

    const int tid  = threadIdx.x;
    const int wid  = tid >> 5;
    const int lane = tid & 31;
    const int rowBase = blockIdx.y * 128;
    const int colBase = blockIdx.x * 128;
    const int z = blockIdx.z;

    const unsigned short* Ah = Ah0 + (size_t)z * AD;
    const unsigned short* Bh = Bh0 + (size_t)z * WD;

    const int wm = (wid & 1) * 64;
    const int wn = (wid >> 1) * 32;

    const uint32_t aoff = (uint32_t)(wm + (lane & 15)) * ROWB + (uint32_t)(lane >> 4) * 16;
    const uint32_t boff = (uint32_t)(wn + (lane & 7) + ((lane >> 4) << 3)) * ROWB
                        + (uint32_t)((lane >> 3) & 1) * 16;

    const unsigned short* gA[4];
    const unsigned short* gB[4];
    uint32_t soa[4], sob[4];
#pragma unroll
    for (int j = 0; j < 4; j++) {
        const int x = tid + 256 * j;
        const int r = x >> 3, c = x & 7;
        gA[j] = Ah + (size_t)(rowBase + r) * DMODEL + c * 8;
        gB[j] = Bh + (size_t)(colBase + r) * DMODEL + c * 8;
        soa[j] = (uint32_t)r * ROWB + (uint32_t)c * 16;
        sob[j] = SUBT + soa[j];
    }

    float acc[4][4][4];
#pragma unroll
    for (int i = 0; i < 4; i++)
#pragma unroll
        for (int j = 0; j < 4; j++)
#pragma unroll
            for (int r = 0; r < 4; r++) acc[i][j][r] = 0.f;

#pragma unroll
    for (int j = 0; j < 4; j++) cpasync16(sbase + soa[j], gA[j]);
#pragma unroll
    for (int j = 0; j < 4; j++) cpasync16(sbase + sob[j], gB[j]);
    asm volatile("cp.async.commit_group;" ::: "memory");
    asm volatile("cp.async.wait_group 0;" ::: "memory");
    __syncthreads();

    for (int it = 0; it < NKIT; ++it) {
        const uint32_t slot = sbase + (it & 1) * SLOT;

        if (it + 1 < NKIT) {
            const int kt = (it + 1) * KSTAGE;
            const uint32_t ns = sbase + ((it + 1) & 1) * SLOT;
#pragma unroll
            for (int j = 0; j < 4; j++) cpasync16(ns + soa[j], gA[j] + kt);
#pragma unroll
            for (int j = 0; j < 4; j++) cpasync16(ns + sob[j], gB[j] + kt);
            asm volatile("cp.async.commit_group;" ::: "memory");
        }

        const uint32_t pA = slot + aoff;
        const uint32_t pB = slot + SUBT + boff;

#pragma unroll
        for (int kk = 0; kk < 4; kk++) {
            const uint32_t ko = (uint32_t)kk * 32;
            uint32_t ah[16], bb[8];
            LDSM_X4(ah[0],  ah[1],  ah[2],  ah[3],  pA + ko);
            LDSM_X4(ah[4],  ah[5],  ah[6],  ah[7],  pA + 16 * ROWB + ko);
            LDSM_X4(ah[8],  ah[9],  ah[10], ah[11], pA + 32 * ROWB + ko);
            LDSM_X4(ah[12], ah[13], ah[14], ah[15], pA + 48 * ROWB + ko);
            LDSM_X4(bb[0], bb[1], bb[2], bb[3], pB + ko);
            LDSM_X4(bb[4], bb[5], bb[6], bb[7], pB + 16 * ROWB + ko);
#pragma unroll
            for (int mt = 0; mt < 4; mt++)
#pragma unroll
                for (int j = 0; j < 4; j++)
                    MMA_F16(acc[mt][j], ah + mt * 4, bb[j * 2], bb[j * 2 + 1]);
        }

        if (it + 1 < NKIT)
            asm volatile("cp.async.wait_group 0;" ::: "memory");
        __syncthreads();
    }

    const int lrow = lane >> 2;
    const int lcol = (lane & 3) * 2;
    const int phi = OUTHALF ? (z != 2) : 0;
#pragma unroll
    for (int mt = 0; mt < 4; mt++) {
#pragma unroll
        for (int j = 0; j < 4; j++) {
            const int col = colBase + wn + j * 8 + lcol;
#pragma unroll
            for (int half = 0; half < 2; half++) {
                const int row = rowBase + wm + mt * 16 + lrow + half * 8;
                float v0 = acc[mt][j][half * 2 + 0];
                float v1 = acc[mt][j][half * 2 + 1];
                if (OUTHALF) {
                    if (phi) {
                        v0 = (v0 > 0.f) ? (v0 + 1.f) : __expf(v0);
                        v1 = (v1 > 0.f) ? (v1 + 1.f) : __expf(v1);
                    }
                    unsigned short* Ch = (unsigned short*)Cv + (size_t)z * AD;
                    *(uint32_t*)(Ch + (size_t)row * DMODEL + col) = cvt_h2(v1, v0);
                } else {
                    v0 += bias[col];
                    v1 += bias[col + 1];
                    *(float2*)((float*)Cv + (size_t)row * DMODEL + col) = make_float2(v0, v1);
                }
            }
        }
    }
}

// ---------------- KV partial via HMMA: KV[d,e] = sum_s K[s,d] V[s,e] ----------------
// Per (bh, chunk of 512 s): A = K^T (trans ldmatrix), B = V (trans ldmatrix),
// 128 threads, 4 warps in 2x2 grid of 32x32 tiles, cp.async 2-slot ring over 64-s blocks.
#define KVROWS 64
#define KVTILE (KVROWS * ROWB)     // 9216 B per 64x64 fp16 tile
#define KVSLOT (2 * KVTILE)        // K + V
#define KVBLKS (SEQ / NCH / KVROWS) // 8

__global__ void __launch_bounds__(128)
kv_hmma_kernel()
{
    __shared__ __align__(16) char sm[2 * KVSLOT];    // 36864 B
    __shared__ float ksred[2][DK];
    const uint32_t sbase = smem_u32(sm);

    const int bh = blockIdx.x;
    const int ch = blockIdx.y;
    const int b = bh >> 4, h = bh & 15;
    const int tid = threadIdx.x;
    const int wid = tid >> 5;
    const int lane = tid & 31;
    const int wm = (wid & 1) * 32;
    const int wn = (wid >> 1) * 32;

    const size_t base = ((size_t)b * SEQ + (size_t)ch * (SEQ / NCH)) * DMODEL + h * DK;
    const unsigned short* gK = g_qkv + AD + base;
    const unsigned short* gV = g_qkv + 2 * AD + base;

    // staging: 512 16B-chunks per tile, 4 per thread
    int cr[4], cc[4];
#pragma unroll
    for (int j = 0; j < 4; j++) { const int x = tid + 128 * j; cr[j] = x >> 3; cc[j] = x & 7; }

    // A (K^T, trans): lanes g0:(s0-7,d0) g1:(s0-7,d8) g2:(s8-15,d0) g3:(s8-15,d8)
    const uint32_t aoff = (uint32_t)((lane & 7) + ((lane >> 4) << 3)) * ROWB
                        + (uint32_t)(wm + ((lane >> 3) & 1) * 8) * 2;
    // B (V, trans): lanes g0:(s0-7,e0) g1:(s8-15,e0) g2:(s0-7,e8) g3:(s8-15,e8)
    const uint32_t boff = (uint32_t)((lane & 7) + (((lane >> 3) & 1) << 3)) * ROWB
                        + (uint32_t)(wn + ((lane >> 4) << 3)) * 2;

    float acc[2][4][4];
#pragma unroll
    for (int i = 0; i < 2; i++)
#pragma unroll
        for (int j = 0; j < 4; j++)
#pragma unroll
            for (int r = 0; r < 4; r++) acc[i][j][r] = 0.f;

    float ks = 0.f;
    const int kd = tid & 63;
    const int khalf = tid >> 6;

    // prologue: block 0
#pragma unroll
    for (int j = 0; j < 4; j++) {
        cpasync16(sbase + cr[j] * ROWB + cc[j] * 16, gK + (size_t)cr[j] * DMODEL + cc[j] * 8);
        cpasync16(sbase + KVTILE + cr[j] * ROWB + cc[j] * 16,
                  gV + (size_t)cr[j] * DMODEL + cc[j] * 8);
    }
    asm volatile("cp.async.commit_group;" ::: "memory");
    asm volatile("cp.async.wait_group 0;" ::: "memory");
    __syncthreads();

    for (int blk = 0; blk < KVBLKS; ++blk) {
        const uint32_t slot = sbase + (blk & 1) * KVSLOT;
        const int slotByte = (blk & 1) * KVSLOT;

        if (blk + 1 < KVBLKS) {
            const size_t soff = (size_t)(blk + 1) * KVROWS * DMODEL;
            const uint32_t ns = sbase + ((blk + 1) & 1) * KVSLOT;
#pragma unroll
            for (int j = 0; j < 4; j++) {
                cpasync16(ns + cr[j] * ROWB + cc[j] * 16,
                          gK + soff + (size_t)cr[j] * DMODEL + cc[j] * 8);
                cpasync16(ns + KVTILE + cr[j] * ROWB + cc[j] * 16,
                          gV + soff + (size_t)cr[j] * DMODEL + cc[j] * 8);
            }
            asm volatile("cp.async.commit_group;" ::: "memory");
        }

        // Ksum accumulation from K tile (fp16 scalar reads)
        {
            const char* kp = sm + slotByte + (khalf * 32) * ROWB + kd * 2;
#pragma unroll 8
            for (int r = 0; r < 32; r++)
                ks += __half2float(*(const __half*)(kp + r * ROWB));
        }

        // HMMA over 4 k16 (s16) steps
#pragma unroll
        for (int kk = 0; kk < 4; kk++) {
            const uint32_t ro = (uint32_t)kk * 16 * ROWB;
            uint32_t a0[4], a1[4], bv0[4], bv1[4];
            LDSM_X4_T(a0[0], a0[1], a0[2], a0[3], slot + ro + aoff);
            LDSM_X4_T(a1[0], a1[1], a1[2], a1[3], slot + ro + aoff + 32);   // d +16 cols
            LDSM_X4_T(bv0[0], bv0[1], bv0[2], bv0[3], slot + KVTILE + ro + boff);
            LDSM_X4_T(bv1[0], bv1[1], bv1[2], bv1[3], slot + KVTILE + ro + boff + 32); // e +16
            MMA_F16(acc[0][0], a0, bv0[0], bv0[1]);
            MMA_F16(acc[0][1], a0, bv0[2], bv0[3]);
            MMA_F16(acc[0][2], a0, bv1[0], bv1[1]);
            MMA_F16(acc[0][3], a0, bv1[2], bv1[3]);
            MMA_F16(acc[1][0], a1, bv0[0], bv0[1]);
            MMA_F16(acc[1][1], a1, bv0[2], bv0[3]);
            MMA_F16(acc[1][2], a1, bv1[0], bv1[1]);
            MMA_F16(acc[1][3], a1, bv1[2], bv1[3]);
        }

        if (blk + 1 < KVBLKS)
            asm volatile("cp.async.wait_group 0;" ::: "memory");
        __syncthreads();
    }

    // write partial KV
    float* pkv = g_pKV + ((size_t)ch * BH + bh) * (DK * DK);
    const int lrow = lane >> 2;
    const int lcol = (lane & 3) * 2;
#pragma unroll
    for (int mt = 0; mt < 2; mt++) {
#pragma unroll
        for (int j = 0; j < 4; j++) {
            const int e = wn + j * 8 + lcol;
#pragma unroll
            for (int half = 0; half < 2; half++) {
                const int d = wm + mt * 16 + lrow + half * 8;
                pkv[d * DK + e]     = acc[mt][j][half * 2 + 0];
                pkv[d * DK + e + 1] = acc[mt][j][half * 2 + 1];
            }
        }
    }

    // combine + write partial Ksum
    ksred[khalf][kd] = ks;
    __syncthreads();
    if (tid < DK)
        g_pKsum[((size_t)ch * BH + bh) * DK + tid] = ksred[0][tid] + ksred[1][tid];
}

// ---------------- KV reduce ----------------
__global__ void kv_reduce_kernel()
{
    const int idx = blockIdx.x * 256 + threadIdx.x;
    const int NKV = BH * DK * DK;
    if (idx < NKV) {
        float s = 0.f;
#pragma unroll
        for (int ch = 0; ch < NCH; ch++) s += g_pKV[(size_t)ch * NKV + idx];
        g_KV[idx] = s;
    } else if (idx < NKV + BH * DK) {
        const int o = idx - NKV;
        float s = 0.f;
#pragma unroll
        for (int ch = 0; ch < NCH; ch++) s += g_pKsum[(size_t)ch * BH * DK + o];
        g_Ksum[o] = s;
    }
}

// ---------------- attention apply: out = (Q @ KV) / (Q . Ksum + eps) -> fp16 ----------------
__global__ void __launch_bounds__(256)
attn_kernel()
{
    const int bh = blockIdx.x;
    const int qt = blockIdx.y;
    const int b = bh >> 4, h = bh & 15;
    const int tid = threadIdx.x;

    __shared__ float KVs[DK * DK];
    __shared__ float Qs[DK][DK + 2];
    __shared__ float Ksm[DK];
    __shared__ float rden[DK];

    const size_t base = ((size_t)b * SEQ + qt * DK) * DMODEL + h * DK;
    const unsigned short* gQ = g_qkv;

#pragma unroll
    for (int l = 0; l < 16; l++) {
        const int idx = tid + l * 256;
        KVs[idx] = g_KV[(size_t)bh * DK * DK + idx];
        const int q = idx >> 6, d = idx & 63;
        Qs[d][q] = __half2float(((const __half*)gQ)[base + (size_t)q * DMODEL + d]);
    }
    if (tid < DK) Ksm[tid] = g_Ksum[bh * DK + tid];
    __syncthreads();

    if (tid < DK) {
        float s = 0.f;
#pragma unroll
        for (int d = 0; d < DK; d++) s += Qs[d][tid] * Ksm[d];
        rden[tid] = 1.f / (s + 1e-6f);
    }
    __syncthreads();

    const int e = tid & 63;
    const int qg = tid >> 6;

    unsigned long long acc[8];
    {
        const unsigned long long z = pack2(0.f, 0.f);
#pragma unroll
        for (int i = 0; i < 8; i++) acc[i] = z;
    }

#pragma unroll 8
    for (int d = 0; d < DK; d++) {
        const float kv = KVs[d * DK + e];
        const unsigned long long kvp = pack2(kv, kv);
#pragma unroll
        for (int t = 0; t < 8; t++) {
            const unsigned long long qp =
                *(const unsigned long long*)&Qs[d][qg * 16 + 2 * t];
            ffma2(acc[t], qp, kvp);
        }
    }

#pragma unroll
    for (int t = 0; t < 8; t++) {
        float v0, v1;
        unpack2(acc[t], v0, v1);
        const int q0 = qg * 16 + 2 * t;
        v0 *= rden[q0];
        v1 *= rden[q0 + 1];
        unsigned short h0, h1;
        asm("cvt.rn.f16.f32 %0, %1;" : "=h"(h0) : "f"(v0));
        asm("cvt.rn.f16.f32 %0, %1;" : "=h"(h1) : "f"(v1));
        g_af16[base + (size_t)q0 * DMODEL + e] = h0;
        g_af16[base + (size_t)(q0 + 1) * DMODEL + e] = h1;
    }
}

// ---------------- launch ----------------
extern "C" void kernel_launch(void* const* d_in, const int* in_sizes, int n_in,
                              void* d_out, int out_size)
{
    const float* query = (const float*)d_in[0];
    const float* key   = (const float*)d_in[1];
    const float* value = (const float*)d_in[2];
    const float* Wq    = (const float*)d_in[3];
    const float* Wk    = (const float*)d_in[4];
    const float* Wv    = (const float*)d_in[5];
    const float* Wo    = (const float*)d_in[6];
    const float* bo    = (const float*)d_in[7];
    float* out = (float*)d_out;
    (void)in_sizes; (void)n_in; (void)out_size;

    unsigned short *xh3, *qkv, *wh, *af16;
    cudaGetSymbolAddress((void**)&xh3, g_xh3);
    cudaGetSymbolAddress((void**)&qkv, g_qkv);
    cudaGetSymbolAddress((void**)&wh, g_wh);
    cudaGetSymbolAddress((void**)&af16, g_af16);

    cudaFuncSetAttribute(gemm_h1<0>, cudaFuncAttributeMaxDynamicSharedMemorySize, GEMM_SMEM);
    cudaFuncSetAttribute(gemm_h1<1>, cudaFuncAttributeMaxDynamicSharedMemorySize, GEMM_SMEM);

    const int n8w = (int)(WD / 8);
    const int n8a = (int)(AD / 8);
    const int cb = 256;

    // quantize: all 4 weights (one launch), all 3 activations (one launch)
    cvt_batch_kernel<<<dim3((n8w + cb - 1) / cb, 4), cb>>>(Wq, Wk, Wv, Wo, wh, WD / 8, n8w);
    cvt_batch_kernel<<<dim3((n8a + cb - 1) / cb, 3), cb>>>(query, key, value, nullptr,
                                                           xh3, AD / 8, n8a);

    // batched QKV projections: z=0 Q(phi), z=1 K(phi), z=2 V
    gemm_h1<1><<<dim3(DMODEL / 128, M_TOTAL / 128, 3), 256, GEMM_SMEM>>>(xh3, wh, qkv, nullptr);

    // linear attention core
    kv_hmma_kernel<<<dim3(BH, NCH), 128>>>();
    kv_reduce_kernel<<<(BH * DK * DK + BH * DK + 255) / 256, 256>>>();
    attn_kernel<<<dim3(BH, SEQ / DK), 256>>>();

    // out = attn @ Wo^T + bo
    gemm_h1<0><<<dim3(DMODEL / 128, M_TOTAL / 128, 1), 256, GEMM_SMEM>>>(af16, wh + 3 * WD,
                                                                         out, bo);
}

// round 16
// speedup vs baseline: 2.5785x; 1.1115x over previous
#include <cuda_runtime.h>
#include <cuda_fp16.h>
#include <cstdint>
#include <cstddef>

// Problem constants
#define DMODEL 1024
#define SEQ    4096
#define BATCH  4
#define NHEAD  16
#define DK     64
#define M_TOTAL (BATCH * SEQ)   // 16384
#define BH      (BATCH * NHEAD) // 64
#define NCH     8
#define AD      ((size_t)M_TOTAL * DMODEL)
#define WD      ((size_t)DMODEL * DMODEL)

// ---------------- scratch (static device globals; no allocation) ----------------
__device__ unsigned short g_xh3[3 * AD];    // fp16 query|key|value
__device__ unsigned short g_qkv[3 * AD];    // fp16 Q|K|V (phi applied to Q,K)
__device__ unsigned short g_af16[AD];       // attn output, fp16
__device__ unsigned short g_wh[4 * WD];     // fp16 Wq|Wk|Wv|Wo
__device__ float g_pKV[(size_t)NCH * BH * DK * DK];
__device__ float g_pKsum[(size_t)NCH * BH * DK];
__device__ unsigned short g_KVh[(size_t)BH * DK * DK];   // reduced KV, fp16
__device__ float g_Ksum[(size_t)BH * DK];

// ---------------- helpers ----------------
__device__ __forceinline__ uint32_t smem_u32(const void* p) {
    uint32_t a;
    asm("{ .reg .u64 t; cvta.to.shared.u64 t, %1; cvt.u32.u64 %0, t; }" : "=r"(a) : "l"(p));
    return a;
}
__device__ __forceinline__ uint32_t cvt_h2(float hi_val, float lo_val) {
    uint32_t r;
    asm("cvt.rn.f16x2.f32 %0, %1, %2;" : "=r"(r) : "f"(hi_val), "f"(lo_val));
    return r;   // low half = lo_val, high half = hi_val
}
__device__ __forceinline__ uint4 cvt8h(const float4& a, const float4& b) {
    uint4 r;
    r.x = cvt_h2(a.y, a.x);
    r.y = cvt_h2(a.w, a.z);
    r.z = cvt_h2(b.y, b.x);
    r.w = cvt_h2(b.w, b.z);
    return r;
}
__device__ __forceinline__ float2 h2f2(uint32_t h) {
    float2 r;
    asm("{ .reg .f16 a, b;\n\t mov.b32 {a, b}, %2;\n\t"
        " cvt.f32.f16 %0, a;\n\t cvt.f32.f16 %1, b; }"
        : "=f"(r.x), "=f"(r.y) : "r"(h));
    return r;
}

#define LDSM_X4(r0, r1, r2, r3, addr) \
    asm volatile("ldmatrix.sync.aligned.m8n8.x4.shared.b16 {%0,%1,%2,%3}, [%4];" \
                 : "=r"(r0), "=r"(r1), "=r"(r2), "=r"(r3) : "r"(addr))

#define LDSM_X4_T(r0, r1, r2, r3, addr) \
    asm volatile("ldmatrix.sync.aligned.m8n8.x4.trans.shared.b16 {%0,%1,%2,%3}, [%4];" \
                 : "=r"(r0), "=r"(r1), "=r"(r2), "=r"(r3) : "r"(addr))

#define MMA_F16(d, a, b0, b1) \
    asm volatile("mma.sync.aligned.m16n8k16.row.col.f32.f16.f16.f32 " \
                 "{%0,%1,%2,%3}, {%4,%5,%6,%7}, {%8,%9}, {%0,%1,%2,%3};" \
                 : "+f"((d)[0]), "+f"((d)[1]), "+f"((d)[2]), "+f"((d)[3]) \
                 : "r"((a)[0]), "r"((a)[1]), "r"((a)[2]), "r"((a)[3]), \
                   "r"(b0), "r"(b1))

__device__ __forceinline__ void cpasync16(uint32_t saddr, const void* g) {
    asm volatile("cp.async.cg.shared.global [%0], [%1], 16;" :: "r"(saddr), "l"(g) : "memory");
}

// ---------------- batched quantize: fp32 -> fp16, up to 4 sources ----------------
__global__ void __launch_bounds__(256)
cvt_batch_kernel(const float* __restrict__ s0, const float* __restrict__ s1,
                 const float* __restrict__ s2, const float* __restrict__ s3,
                 unsigned short* __restrict__ dst, size_t perN8, int n8)
{
    const int i = blockIdx.x * 256 + threadIdx.x;
    if (i >= n8) return;
    const float* srcs[4] = {s0, s1, s2, s3};
    const float* in = srcs[blockIdx.y];
    unsigned short* outp = dst + blockIdx.y * perN8 * 8;
    float4 a = ((const float4*)in)[2 * i];
    float4 b = ((const float4*)in)[2 * i + 1];
    ((uint4*)outp)[i] = cvt8h(a, b);
}

// ---------------- HMMA GEMM: C[m,n] = sum_k A[m,k] * W[n,k] (+epilogue) ----------------
// CTA 128x128, 256 threads (8 warps, warp tile 64x32), K-stage 64 -> 2 CTAs/SM.
// blockIdx.z batches GEMMs. OUTHALF=1: fp16 C, phi unless z==2. OUTHALF=0: fp32 C + bias.
#define KSTAGE 64
#define NKIT   (DMODEL / KSTAGE)           // 16
#define ROWB   144                         // 128B row + 16B pad: conflict-free ldmatrix
#define SUBT   (128 * ROWB)                // 18432 B: 128x64 fp16 sub-tile (A or B)
#define SLOT   (2 * SUBT)                  // 36864
#define GEMM_SMEM (2 * SLOT)               // 73728

template <int OUTHALF>
__global__ void __launch_bounds__(256, 2)
gemm_h1(const unsigned short* __restrict__ Ah0, const unsigned short* __restrict__ Bh0,
        void* __restrict__ Cv, const float* __restrict__ bias)
{
    extern __shared__ char smem[];
    const uint32_t sbase = smem_u32(smem);

    const int tid  = threadIdx.x;
    const int wid  = tid >> 5;
    const int lane = tid & 31;
    const int rowBase = blockIdx.y * 128;
    const int colBase = blockIdx.x * 128;
    const int z = blockIdx.z;

    const unsigned short* Ah = Ah0 + (size_t)z * AD;
    const unsigned short* Bh = Bh0 + (size_t)z * WD;

    const int wm = (wid & 1) * 64;
    const int wn = (wid >> 1) * 32;

    const uint32_t aoff = (uint32_t)(wm + (lane & 15)) * ROWB + (uint32_t)(lane >> 4) * 16;
    const uint32_t boff = (uint32_t)(wn + (lane & 7) + ((lane >> 4) << 3)) * ROWB
                        + (uint32_t)((lane >> 3) & 1) * 16;

    const unsigned short* gA[4];
    const unsigned short* gB[4];
    uint32_t soa[4], sob[4];
#pragma unroll
    for (int j = 0; j < 4; j++) {
        const int x = tid + 256 * j;
        const int r = x >> 3, c = x & 7;
        gA[j] = Ah + (size_t)(rowBase + r) * DMODEL + c * 8;
        gB[j] = Bh + (size_t)(colBase + r) * DMODEL + c * 8;
        soa[j] = (uint32_t)r * ROWB + (uint32_t)c * 16;
        sob[j] = SUBT + soa[j];
    }

    float acc[4][4][4];
#pragma unroll
    for (int i = 0; i < 4; i++)
#pragma unroll
        for (int j = 0; j < 4; j++)
#pragma unroll
            for (int r = 0; r < 4; r++) acc[i][j][r] = 0.f;

#pragma unroll
    for (int j = 0; j < 4; j++) cpasync16(sbase + soa[j], gA[j]);
#pragma unroll
    for (int j = 0; j < 4; j++) cpasync16(sbase + sob[j], gB[j]);
    asm volatile("cp.async.commit_group;" ::: "memory");
    asm volatile("cp.async.wait_group 0;" ::: "memory");
    __syncthreads();

    for (int it = 0; it < NKIT; ++it) {
        const uint32_t slot = sbase + (it & 1) * SLOT;

        if (it + 1 < NKIT) {
            const int kt = (it + 1) * KSTAGE;
            const uint32_t ns = sbase + ((it + 1) & 1) * SLOT;
#pragma unroll
            for (int j = 0; j < 4; j++) cpasync16(ns + soa[j], gA[j] + kt);
#pragma unroll
            for (int j = 0; j < 4; j++) cpasync16(ns + sob[j], gB[j] + kt);
            asm volatile("cp.async.commit_group;" ::: "memory");
        }

        const uint32_t pA = slot + aoff;
        const uint32_t pB = slot + SUBT + boff;

#pragma unroll
        for (int kk = 0; kk < 4; kk++) {
            const uint32_t ko = (uint32_t)kk * 32;
            uint32_t ah[16], bb[8];
            LDSM_X4(ah[0],  ah[1],  ah[2],  ah[3],  pA + ko);
            LDSM_X4(ah[4],  ah[5],  ah[6],  ah[7],  pA + 16 * ROWB + ko);
            LDSM_X4(ah[8],  ah[9],  ah[10], ah[11], pA + 32 * ROWB + ko);
            LDSM_X4(ah[12], ah[13], ah[14], ah[15], pA + 48 * ROWB + ko);
            LDSM_X4(bb[0], bb[1], bb[2], bb[3], pB + ko);
            LDSM_X4(bb[4], bb[5], bb[6], bb[7], pB + 16 * ROWB + ko);
#pragma unroll
            for (int mt = 0; mt < 4; mt++)
#pragma unroll
                for (int j = 0; j < 4; j++)
                    MMA_F16(acc[mt][j], ah + mt * 4, bb[j * 2], bb[j * 2 + 1]);
        }

        if (it + 1 < NKIT)
            asm volatile("cp.async.wait_group 0;" ::: "memory");
        __syncthreads();
    }

    const int lrow = lane >> 2;
    const int lcol = (lane & 3) * 2;
    const int phi = OUTHALF ? (z != 2) : 0;
#pragma unroll
    for (int mt = 0; mt < 4; mt++) {
#pragma unroll
        for (int j = 0; j < 4; j++) {
            const int col = colBase + wn + j * 8 + lcol;
#pragma unroll
            for (int half = 0; half < 2; half++) {
                const int row = rowBase + wm + mt * 16 + lrow + half * 8;
                float v0 = acc[mt][j][half * 2 + 0];
                float v1 = acc[mt][j][half * 2 + 1];
                if (OUTHALF) {
                    if (phi) {
                        v0 = (v0 > 0.f) ? (v0 + 1.f) : __expf(v0);
                        v1 = (v1 > 0.f) ? (v1 + 1.f) : __expf(v1);
                    }
                    unsigned short* Ch = (unsigned short*)Cv + (size_t)z * AD;
                    *(uint32_t*)(Ch + (size_t)row * DMODEL + col) = cvt_h2(v1, v0);
                } else {
                    v0 += bias[col];
                    v1 += bias[col + 1];
                    *(float2*)((float*)Cv + (size_t)row * DMODEL + col) = make_float2(v0, v1);
                }
            }
        }
    }
}

// ---------------- KV partial via HMMA: KV[d,e] = sum_s K[s,d] V[s,e] ----------------
#define KVROWS 64
#define KVTILE (KVROWS * ROWB)     // 9216 B per 64x64 fp16 tile
#define KVSLOT (2 * KVTILE)        // K + V
#define KVBLKS (SEQ / NCH / KVROWS) // 8

__global__ void __launch_bounds__(128)
kv_hmma_kernel()
{
    __shared__ __align__(16) char sm[2 * KVSLOT];    // 36864 B
    __shared__ float ksred[2][DK];
    const uint32_t sbase = smem_u32(sm);

    const int bh = blockIdx.x;
    const int ch = blockIdx.y;
    const int b = bh >> 4, h = bh & 15;
    const int tid = threadIdx.x;
    const int wid = tid >> 5;
    const int lane = tid & 31;
    const int wm = (wid & 1) * 32;
    const int wn = (wid >> 1) * 32;

    const size_t base = ((size_t)b * SEQ + (size_t)ch * (SEQ / NCH)) * DMODEL + h * DK;
    const unsigned short* gK = g_qkv + AD + base;
    const unsigned short* gV = g_qkv + 2 * AD + base;

    int cr[4], cc[4];
#pragma unroll
    for (int j = 0; j < 4; j++) { const int x = tid + 128 * j; cr[j] = x >> 3; cc[j] = x & 7; }

    const uint32_t aoff = (uint32_t)((lane & 7) + ((lane >> 4) << 3)) * ROWB
                        + (uint32_t)(wm + ((lane >> 3) & 1) * 8) * 2;
    const uint32_t boff = (uint32_t)((lane & 7) + (((lane >> 3) & 1) << 3)) * ROWB
                        + (uint32_t)(wn + ((lane >> 4) << 3)) * 2;

    float acc[2][4][4];
#pragma unroll
    for (int i = 0; i < 2; i++)
#pragma unroll
        for (int j = 0; j < 4; j++)
#pragma unroll
            for (int r = 0; r < 4; r++) acc[i][j][r] = 0.f;

    float ks = 0.f;
    const int kd = tid & 63;
    const int khalf = tid >> 6;

#pragma unroll
    for (int j = 0; j < 4; j++) {
        cpasync16(sbase + cr[j] * ROWB + cc[j] * 16, gK + (size_t)cr[j] * DMODEL + cc[j] * 8);
        cpasync16(sbase + KVTILE + cr[j] * ROWB + cc[j] * 16,
                  gV + (size_t)cr[j] * DMODEL + cc[j] * 8);
    }
    asm volatile("cp.async.commit_group;" ::: "memory");
    asm volatile("cp.async.wait_group 0;" ::: "memory");
    __syncthreads();

    for (int blk = 0; blk < KVBLKS; ++blk) {
        const uint32_t slot = sbase + (blk & 1) * KVSLOT;
        const int slotByte = (blk & 1) * KVSLOT;

        if (blk + 1 < KVBLKS) {
            const size_t soff = (size_t)(blk + 1) * KVROWS * DMODEL;
            const uint32_t ns = sbase + ((blk + 1) & 1) * KVSLOT;
#pragma unroll
            for (int j = 0; j < 4; j++) {
                cpasync16(ns + cr[j] * ROWB + cc[j] * 16,
                          gK + soff + (size_t)cr[j] * DMODEL + cc[j] * 8);
                cpasync16(ns + KVTILE + cr[j] * ROWB + cc[j] * 16,
                          gV + soff + (size_t)cr[j] * DMODEL + cc[j] * 8);
            }
            asm volatile("cp.async.commit_group;" ::: "memory");
        }

        {
            const char* kp = sm + slotByte + (khalf * 32) * ROWB + kd * 2;
#pragma unroll 8
            for (int r = 0; r < 32; r++)
                ks += __half2float(*(const __half*)(kp + r * ROWB));
        }

#pragma unroll
        for (int kk = 0; kk < 4; kk++) {
            const uint32_t ro = (uint32_t)kk * 16 * ROWB;
            uint32_t a0[4], a1[4], bv0[4], bv1[4];
            LDSM_X4_T(a0[0], a0[1], a0[2], a0[3], slot + ro + aoff);
            LDSM_X4_T(a1[0], a1[1], a1[2], a1[3], slot + ro + aoff + 32);
            LDSM_X4_T(bv0[0], bv0[1], bv0[2], bv0[3], slot + KVTILE + ro + boff);
            LDSM_X4_T(bv1[0], bv1[1], bv1[2], bv1[3], slot + KVTILE + ro + boff + 32);
            MMA_F16(acc[0][0], a0, bv0[0], bv0[1]);
            MMA_F16(acc[0][1], a0, bv0[2], bv0[3]);
            MMA_F16(acc[0][2], a0, bv1[0], bv1[1]);
            MMA_F16(acc[0][3], a0, bv1[2], bv1[3]);
            MMA_F16(acc[1][0], a1, bv0[0], bv0[1]);
            MMA_F16(acc[1][1], a1, bv0[2], bv0[3]);
            MMA_F16(acc[1][2], a1, bv1[0], bv1[1]);
            MMA_F16(acc[1][3], a1, bv1[2], bv1[3]);
        }

        if (blk + 1 < KVBLKS)
            asm volatile("cp.async.wait_group 0;" ::: "memory");
        __syncthreads();
    }

    float* pkv = g_pKV + ((size_t)ch * BH + bh) * (DK * DK);
    const int lrow = lane >> 2;
    const int lcol = (lane & 3) * 2;
#pragma unroll
    for (int mt = 0; mt < 2; mt++) {
#pragma unroll
        for (int j = 0; j < 4; j++) {
            const int e = wn + j * 8 + lcol;
#pragma unroll
            for (int half = 0; half < 2; half++) {
                const int d = wm + mt * 16 + lrow + half * 8;
                pkv[d * DK + e]     = acc[mt][j][half * 2 + 0];
                pkv[d * DK + e + 1] = acc[mt][j][half * 2 + 1];
            }
        }
    }

    ksred[khalf][kd] = ks;
    __syncthreads();
    if (tid < DK)
        g_pKsum[((size_t)ch * BH + bh) * DK + tid] = ksred[0][tid] + ksred[1][tid];
}

// ---------------- KV reduce: fp32 partials -> fp16 KV + fp32 Ksum ----------------
__global__ void kv_reduce_kernel()
{
    const int idx = blockIdx.x * 256 + threadIdx.x;
    const int NKV = BH * DK * DK;
    if (idx < NKV) {
        float s = 0.f;
#pragma unroll
        for (int ch = 0; ch < NCH; ch++) s += g_pKV[(size_t)ch * NKV + idx];
        unsigned short hs;
        asm("cvt.rn.f16.f32 %0, %1;" : "=h"(hs) : "f"(s));
        g_KVh[idx] = hs;
    } else if (idx < NKV + BH * DK) {
        const int o = idx - NKV;
        float s = 0.f;
#pragma unroll
        for (int ch = 0; ch < NCH; ch++) s += g_pKsum[(size_t)ch * BH * DK + o];
        g_Ksum[o] = s;
    }
}

// ---------------- attention apply via HMMA: out = (Q @ KV) * rden -> fp16 ----------------
// CTA: 256 q rows x 64 e, 256 threads (8 warps along M, warp tile 32x64).
// A = Q (normal ldmatrix, k=d), B = KV fp16 [d][e] (trans ldmatrix, rows=k).
#define ATROWS 256
#define AQT    (ATROWS * ROWB)     // 36864 B Q tile
#define AKVT   (DK * ROWB)         // 9216 B KV tile

__global__ void __launch_bounds__(256)
attn_hmma_kernel()
{
    __shared__ __align__(16) char sm[AQT + AKVT];
    __shared__ float Ksm[DK];
    __shared__ float rden[ATROWS];
    const uint32_t sbase = smem_u32(sm);

    const int bh = blockIdx.x;
    const int qt = blockIdx.y;
    const int b = bh >> 4, h = bh & 15;
    const int tid = threadIdx.x;
    const int wid = tid >> 5;
    const int lane = tid & 31;
    const int wm = wid * 32;

    const size_t base = ((size_t)b * SEQ + (size_t)qt * ATROWS) * DMODEL + h * DK;
    const unsigned short* gQ = g_qkv + base;

    // stage Q tile: 2048 16B-chunks, 8 per thread
#pragma unroll
    for (int j = 0; j < 8; j++) {
        const int x = tid + 256 * j;
        const int r = x >> 3, c = x & 7;
        cpasync16(sbase + (uint32_t)r * ROWB + (uint32_t)c * 16,
                  gQ + (size_t)r * DMODEL + c * 8);
    }
    // stage KV tile: 512 chunks, 2 per thread
#pragma unroll
    for (int j = 0; j < 2; j++) {
        const int x = tid + 256 * j;
        const int r = x >> 3, c = x & 7;
        cpasync16(sbase + AQT + (uint32_t)r * ROWB + (uint32_t)c * 16,
                  g_KVh + (size_t)bh * DK * DK + (size_t)r * DK + c * 8);
    }
    if (tid < DK) Ksm[tid] = g_Ksum[bh * DK + tid];
    asm volatile("cp.async.commit_group;" ::: "memory");
    asm volatile("cp.async.wait_group 0;" ::: "memory");
    __syncthreads();

    // den: thread tid handles q row = tid
    {
        const char* qp = sm + (uint32_t)tid * ROWB;
        float s = 0.f;
#pragma unroll
        for (int c = 0; c < 32; c++) {
            const float2 qq = h2f2(*(const uint32_t*)(qp + c * 4));
            s += qq.x * Ksm[2 * c] + qq.y * Ksm[2 * c + 1];
        }
        rden[tid] = 1.f / (s + 1e-6f);
    }
    __syncthreads();

    // MMA: warp tile 32q x 64e, k = 64 (4 k16 steps)
    const uint32_t aoff = (uint32_t)(wm + (lane & 15)) * ROWB + (uint32_t)(lane >> 4) * 16;
    const uint32_t boff = (uint32_t)((lane & 7) + (((lane >> 3) & 1) << 3)) * ROWB
                        + (uint32_t)((lane >> 4) << 3) * 2;

    float acc[2][8][4];
#pragma unroll
    for (int i = 0; i < 2; i++)
#pragma unroll
        for (int j = 0; j < 8; j++)
#pragma unroll
            for (int r = 0; r < 4; r++) acc[i][j][r] = 0.f;

#pragma unroll
    for (int kk = 0; kk < 4; kk++) {
        const uint32_t ko = (uint32_t)kk * 32;           // A: 16 d = 32 bytes
        const uint32_t ro = (uint32_t)kk * 16 * ROWB;    // B: 16 d rows
        uint32_t ah[8];
        LDSM_X4(ah[0], ah[1], ah[2], ah[3], sbase + aoff + ko);
        LDSM_X4(ah[4], ah[5], ah[6], ah[7], sbase + aoff + 16 * ROWB + ko);
#pragma unroll
        for (int g = 0; g < 4; g++) {                    // e groups of 16
            uint32_t bv[4];
            LDSM_X4_T(bv[0], bv[1], bv[2], bv[3], sbase + AQT + ro + boff + g * 32);
            MMA_F16(acc[0][2 * g],     ah,     bv[0], bv[1]);
            MMA_F16(acc[0][2 * g + 1], ah,     bv[2], bv[3]);
            MMA_F16(acc[1][2 * g],     ah + 4, bv[0], bv[1]);
            MMA_F16(acc[1][2 * g + 1], ah + 4, bv[2], bv[3]);
        }
    }

    // epilogue: scale by rden, write fp16
    const int lrow = lane >> 2;
    const int lcol = (lane & 3) * 2;
    unsigned short* outp = g_af16 + base;
#pragma unroll
    for (int mt = 0; mt < 2; mt++) {
#pragma unroll
        for (int j = 0; j < 8; j++) {
            const int col = j * 8 + lcol;
#pragma unroll
            for (int half = 0; half < 2; half++) {
                const int row = wm + mt * 16 + lrow + half * 8;
                const float rd = rden[row];
                const float v0 = acc[mt][j][half * 2 + 0] * rd;
                const float v1 = acc[mt][j][half * 2 + 1] * rd;
                *(uint32_t*)(outp + (size_t)row * DMODEL + col) = cvt_h2(v1, v0);
            }
        }
    }
}

// ---------------- launch ----------------
extern "C" void kernel_launch(void* const* d_in, const int* in_sizes, int n_in,
                              void* d_out, int out_size)
{
    const float* query = (const float*)d_in[0];
    const float* key   = (const float*)d_in[1];
    const float* value = (const float*)d_in[2];
    const float* Wq    = (const float*)d_in[3];
    const float* Wk    = (const float*)d_in[4];
    const float* Wv    = (const float*)d_in[5];
    const float* Wo    = (const float*)d_in[6];
    const float* bo    = (const float*)d_in[7];
    float* out = (float*)d_out;
    (void)in_sizes; (void)n_in; (void)out_size;

    unsigned short *xh3, *qkv, *wh, *af16;
    cudaGetSymbolAddress((void**)&xh3, g_xh3);
    cudaGetSymbolAddress((void**)&qkv, g_qkv);
    cudaGetSymbolAddress((void**)&wh, g_wh);
    cudaGetSymbolAddress((void**)&af16, g_af16);

    cudaFuncSetAttribute(gemm_h1<0>, cudaFuncAttributeMaxDynamicSharedMemorySize, GEMM_SMEM);
    cudaFuncSetAttribute(gemm_h1<1>, cudaFuncAttributeMaxDynamicSharedMemorySize, GEMM_SMEM);

    const int n8w = (int)(WD / 8);
    const int n8a = (int)(AD / 8);
    const int cb = 256;

    // quantize: all 4 weights (one launch), all 3 activations (one launch)
    cvt_batch_kernel<<<dim3((n8w + cb - 1) / cb, 4), cb>>>(Wq, Wk, Wv, Wo, wh, WD / 8, n8w);
    cvt_batch_kernel<<<dim3((n8a + cb - 1) / cb, 3), cb>>>(query, key, value, nullptr,
                                                           xh3, AD / 8, n8a);

    // batched QKV projections: z=0 Q(phi), z=1 K(phi), z=2 V
    gemm_h1<1><<<dim3(DMODEL / 128, M_TOTAL / 128, 3), 256, GEMM_SMEM>>>(xh3, wh, qkv, nullptr);

    // linear attention core (all HMMA)
    kv_hmma_kernel<<<dim3(BH, NCH), 128>>>();
    kv_reduce_kernel<<<(BH * DK * DK + BH * DK + 255) / 256, 256>>>();
    attn_hmma_kernel<<<dim3(BH, SEQ / ATROWS), 256>>>();

    // out = attn @ Wo^T + bo
    gemm_h1<0><<<dim3(DMODEL / 128, M_TOTAL / 128, 1), 256, GEMM_SMEM>>>(af16, wh + 3 * WD,
                                                                         out, bo);
}